// round 1
// baseline (speedup 1.0000x reference)
#include <cuda_runtime.h>
#include <math.h>

#define BATCH 2
#define LSEQ 2048
#define DMODEL 1024
#define NHEAD 16
#define DHEAD 64
#define UTOP 40
#define MROWS (BATCH*LSEQ)          // 4096
#define BHL (BATCH*NHEAD*LSEQ)      // 65536

// ---------------- scratch (static device globals; no allocation) -------------
__device__ float g_Q[BATCH*NHEAD*LSEQ*DHEAD];        // (B,H,L,DH) 16MB
__device__ float g_K[BATCH*NHEAD*LSEQ*DHEAD];        // 16MB
__device__ float g_V[BATCH*NHEAD*LSEQ*DHEAD];        // 16MB
__device__ float g_M[BHL];                           // sparsity measure
__device__ int   g_top[BATCH*NHEAD*UTOP];            // top-u query indices
__device__ float g_ctx[BATCH*NHEAD*UTOP*DHEAD];      // ctx_update
__device__ float g_vmean[BATCH*NHEAD*DHEAD];         // V mean over L
__device__ float g_context[BATCH*LSEQ*DMODEL];       // (B,L,H,DH) 16MB

// ---------------- GEMM: C[m,n] = sum_k X[m,k]*W[n,k] + bias[n] ---------------
// 128x128 tile, BK=16, 256 threads, 8x8 microtile.
// MODE 0: write to g_Q with (B,H,L,DH) remap
// MODE 1: write to g_K / g_V (N=2048 split)
// MODE 2: X := g_context, plain row-major write to out (d_out)
template<int MODE>
__global__ void gemm128(const float* __restrict__ Xin, const float* __restrict__ W,
                        const float* __restrict__ bias, float* __restrict__ out)
{
    const int K = DMODEL;
    const float* X = (MODE == 2) ? (const float*)g_context : Xin;
    __shared__ float As[16][132];
    __shared__ float Bs[16][132];
    const int m0 = blockIdx.y * 128;
    const int n0 = blockIdx.x * 128;
    const int t  = threadIdx.x;
    const int tx = t & 15, ty = t >> 4;

    float c[8][8];
    #pragma unroll
    for (int i = 0; i < 8; i++)
        #pragma unroll
        for (int j = 0; j < 8; j++) c[i][j] = 0.f;

    for (int k0 = 0; k0 < K; k0 += 16) {
        // load A tile (128x16) and B tile (128x16) as float4
        #pragma unroll
        for (int i = 0; i < 2; i++) {
            int idx = t + i * 256;          // 0..511
            int row = idx >> 2;             // 0..127
            int c4  = idx & 3;              // 0..3
            float4 av = *reinterpret_cast<const float4*>(&X[(size_t)(m0+row)*K + k0 + c4*4]);
            float4 bv = *reinterpret_cast<const float4*>(&W[(size_t)(n0+row)*K + k0 + c4*4]);
            As[c4*4+0][row] = av.x; As[c4*4+1][row] = av.y;
            As[c4*4+2][row] = av.z; As[c4*4+3][row] = av.w;
            Bs[c4*4+0][row] = bv.x; Bs[c4*4+1][row] = bv.y;
            Bs[c4*4+2][row] = bv.z; Bs[c4*4+3][row] = bv.w;
        }
        __syncthreads();
        #pragma unroll
        for (int kk = 0; kk < 16; kk++) {
            float a[8], b[8];
            #pragma unroll
            for (int i = 0; i < 8; i++) a[i] = As[kk][i*16 + ty];
            #pragma unroll
            for (int j = 0; j < 8; j++) b[j] = Bs[kk][j*16 + tx];
            #pragma unroll
            for (int i = 0; i < 8; i++)
                #pragma unroll
                for (int j = 0; j < 8; j++)
                    c[i][j] = fmaf(a[i], b[j], c[i][j]);
        }
        __syncthreads();
    }

    #pragma unroll
    for (int i = 0; i < 8; i++) {
        int m  = m0 + i*16 + ty;
        int b_ = m / LSEQ, l = m % LSEQ;
        #pragma unroll
        for (int j = 0; j < 8; j++) {
            int n = n0 + j*16 + tx;
            float v = c[i][j] + bias[n];
            if (MODE == 0) {
                int h = n >> 6, dh = n & 63;
                g_Q[(((size_t)(b_*NHEAD+h))*LSEQ + l)*DHEAD + dh] = v;
            } else if (MODE == 1) {
                float* dst = (n < DMODEL) ? g_K : g_V;
                int nn = n & (DMODEL-1);
                int h = nn >> 6, dh = nn & 63;
                dst[(((size_t)(b_*NHEAD+h))*LSEQ + l)*DHEAD + dh] = v;
            } else {
                out[(size_t)m*DMODEL + n] = v;
            }
        }
    }
}

// ---------------- M[b,h,l] = max_u(QK) - mean_u(QK) over U sampled keys ------
__global__ void score_m_kernel(const int* __restrict__ idxs)
{
    int warp = (blockIdx.x * blockDim.x + threadIdx.x) >> 5;
    int lane = threadIdx.x & 31;
    if (warp >= BHL) return;
    int l  = warp % LSEQ;
    int bh = warp / LSEQ;
    const float* qr = g_Q + (size_t)warp * DHEAD;
    float q0 = qr[lane], q1 = qr[lane + 32];
    float mx = -1e30f, sm = 0.f;
    #pragma unroll 4
    for (int u = 0; u < UTOP; u++) {
        int ki = idxs[l*UTOP + u];
        const float* kr = g_K + ((size_t)bh*LSEQ + ki)*DHEAD;
        float s = q0*kr[lane] + q1*kr[lane + 32];
        #pragma unroll
        for (int o = 16; o; o >>= 1) s += __shfl_xor_sync(0xffffffffu, s, o);
        mx = fmaxf(mx, s);
        sm += s;
    }
    if (lane == 0) g_M[warp] = mx - sm * (1.0f / UTOP);
}

// ---------------- iterative top-U per (b,h) ---------------------------------
__global__ void topk_kernel()
{
    int bh = blockIdx.x;
    __shared__ float vals[LSEQ];
    __shared__ float rv[256];
    __shared__ int   ri[256];
    int t = threadIdx.x;
    for (int i = t; i < LSEQ; i += 256) vals[i] = g_M[(size_t)bh*LSEQ + i];
    __syncthreads();
    for (int it = 0; it < UTOP; it++) {
        float bv = -1e30f; int bi = 0;
        for (int i = t; i < LSEQ; i += 256) {
            float v = vals[i];
            if (v > bv) { bv = v; bi = i; }
        }
        rv[t] = bv; ri[t] = bi;
        __syncthreads();
        for (int s = 128; s; s >>= 1) {
            if (t < s) {
                if (rv[t+s] > rv[t] || (rv[t+s] == rv[t] && ri[t+s] < ri[t])) {
                    rv[t] = rv[t+s]; ri[t] = ri[t+s];
                }
            }
            __syncthreads();
        }
        if (t == 0) { g_top[bh*UTOP + it] = ri[0]; vals[ri[0]] = -1e30f; }
        __syncthreads();
    }
}

// ---------------- V mean over L ----------------------------------------------
__global__ void vmean_kernel()
{
    int bh = blockIdx.x;
    int dh = threadIdx.x;
    float s = 0.f;
    for (int l = 0; l < LSEQ; l++)
        s += g_V[((size_t)bh*LSEQ + l)*DHEAD + dh];
    g_vmean[bh*DHEAD + dh] = s * (1.0f / LSEQ);
}

// ---------------- fill context with broadcast V-mean -------------------------
__global__ void fill_ctx_kernel()
{
    int idx = blockIdx.x * blockDim.x + threadIdx.x;   // over B*L*H*DH
    int dh = idx & 63;
    int h  = (idx >> 6) & 15;
    int bl = idx >> 10;
    int b_ = bl / LSEQ;
    g_context[idx] = g_vmean[(b_*NHEAD + h)*DHEAD + dh];
}

// ---------------- full attention for the selected U queries ------------------
__global__ void attn_kernel()
{
    int gid = blockIdx.x;            // B*H*U
    int bh  = gid / UTOP, u = gid % UTOP;
    int t   = threadIdx.x;
    __shared__ float q[DHEAD];
    __shared__ float sc[LSEQ];
    __shared__ float red[256];
    __shared__ float part[4][64];

    int ql = g_top[bh*UTOP + u];
    if (t < DHEAD) q[t] = g_Q[((size_t)bh*LSEQ + ql)*DHEAD + t];
    __syncthreads();

    const float4* q4 = reinterpret_cast<const float4*>(q);
    for (int k = t; k < LSEQ; k += 256) {
        const float4* kr = reinterpret_cast<const float4*>(g_K + ((size_t)bh*LSEQ + k)*DHEAD);
        float s = 0.f;
        #pragma unroll
        for (int i = 0; i < 16; i++) {
            float4 kv = kr[i]; float4 qv = q4[i];
            s += kv.x*qv.x + kv.y*qv.y + kv.z*qv.z + kv.w*qv.w;
        }
        sc[k] = s * 0.125f;          // 1/sqrt(64)
    }
    __syncthreads();

    // softmax max
    float mx = -1e30f;
    for (int k = t; k < LSEQ; k += 256) mx = fmaxf(mx, sc[k]);
    red[t] = mx; __syncthreads();
    for (int s = 128; s; s >>= 1) { if (t < s) red[t] = fmaxf(red[t], red[t+s]); __syncthreads(); }
    mx = red[0]; __syncthreads();

    // exp + sum
    float sme = 0.f;
    for (int k = t; k < LSEQ; k += 256) { float e = __expf(sc[k] - mx); sc[k] = e; sme += e; }
    red[t] = sme; __syncthreads();
    for (int s = 128; s; s >>= 1) { if (t < s) red[t] += red[t+s]; __syncthreads(); }
    float inv = 1.0f / red[0];
    __syncthreads();

    // attn @ V : thread t -> dh = t&63, k-chunk = t>>6
    int dh = t & 63, chunk = t >> 6;
    float acc = 0.f;
    int kb = chunk * 512;
    for (int k = kb; k < kb + 512; k++)
        acc += sc[k] * g_V[((size_t)bh*LSEQ + k)*DHEAD + dh];
    part[chunk][dh] = acc;
    __syncthreads();
    if (t < 64)
        g_ctx[((size_t)bh*UTOP + u)*DHEAD + t] =
            (part[0][t] + part[1][t] + part[2][t] + part[3][t]) * inv;
}

// ---------------- scatter ctx_update into context ----------------------------
__global__ void scatter_kernel()
{
    int idx = blockIdx.x * blockDim.x + threadIdx.x;   // B*H*U*64
    int dh = idx & 63;
    int u  = (idx >> 6) % UTOP;
    int bh = idx / (UTOP * 64);
    int b_ = bh / NHEAD, h = bh % NHEAD;
    int l  = g_top[bh*UTOP + u];
    g_context[(((size_t)(b_*LSEQ + l))*NHEAD + h)*DHEAD + dh] = g_ctx[idx];
}

// -----------------------------------------------------------------------------
extern "C" void kernel_launch(void* const* d_in, const int* in_sizes, int n_in,
                              void* d_out, int out_size)
{
    const float* x    = (const float*)d_in[0];
    const float* Wq   = (const float*)d_in[1];
    const float* bq   = (const float*)d_in[2];
    const float* Wkv  = (const float*)d_in[3];
    const float* bkv  = (const float*)d_in[4];
    const float* Wout = (const float*)d_in[5];
    const float* bout = (const float*)d_in[6];
    const int*   idxs = (const int*)d_in[7];
    float* out = (float*)d_out;

    // Q projection: (4096 x 1024) x (1024 x 1024)^T
    gemm128<0><<<dim3(DMODEL/128, MROWS/128), 256>>>(x, Wq, bq, nullptr);
    // KV projection: (4096 x 2048)
    gemm128<1><<<dim3(2*DMODEL/128, MROWS/128), 256>>>(x, Wkv, bkv, nullptr);
    // sparsity measure M
    score_m_kernel<<<BHL/8, 256>>>(idxs);
    // top-U per (b,h)
    topk_kernel<<<BATCH*NHEAD, 256>>>();
    // V mean
    vmean_kernel<<<BATCH*NHEAD, DHEAD>>>();
    // fill context with broadcast mean
    fill_ctx_kernel<<<(BATCH*LSEQ*DMODEL)/256, 256>>>();
    // full attention for selected queries
    attn_kernel<<<BATCH*NHEAD*UTOP, 256>>>();
    // scatter updates
    scatter_kernel<<<(BATCH*NHEAD*UTOP*DHEAD)/256, 256>>>();
    // output projection
    gemm128<2><<<dim3(DMODEL/128, MROWS/128), 256>>>(nullptr, Wout, bout, out);
}

// round 3
// speedup vs baseline: 2.5993x; 2.5993x over previous
#include <cuda_runtime.h>
#include <cuda_bf16.h>
#include <cstdint>
#include <math.h>

#define BATCH 2
#define LSEQ 2048
#define DMODEL 1024
#define NHEAD 16
#define DHEAD 64
#define UTOP 40
#define MROWS (BATCH*LSEQ)          // 4096
#define BHL (BATCH*NHEAD*LSEQ)      // 65536
#define KSPLIT 8
#define KS_KEYS (LSEQ/KSPLIT)       // 256

// ---------------- scratch (static device globals; no allocation) -------------
__device__ float g_Q[BATCH*NHEAD*LSEQ*DHEAD];
__device__ float g_K[BATCH*NHEAD*LSEQ*DHEAD];
__device__ float g_V[BATCH*NHEAD*LSEQ*DHEAD];
__device__ float g_M[BHL];
__device__ int   g_top[BATCH*NHEAD*UTOP];
__device__ float g_ctx[BATCH*NHEAD*UTOP*DHEAD];
__device__ float g_vpart[BATCH*NHEAD*KSPLIT*DHEAD];
__device__ float g_vmean[BATCH*NHEAD*DHEAD];
__device__ float g_context[BATCH*LSEQ*DMODEL];
// bf16 split operands for tensor-core GEMMs
__device__ __nv_bfloat16 g_xhi[MROWS*DMODEL], g_xlo[MROWS*DMODEL];
__device__ __nv_bfloat16 g_whi[3*DMODEL*DMODEL], g_wlo[3*DMODEL*DMODEL];   // [Wq;Wkv]
__device__ __nv_bfloat16 g_wohi[DMODEL*DMODEL], g_wolo[DMODEL*DMODEL];
__device__ __nv_bfloat16 g_chi[MROWS*DMODEL], g_clo[MROWS*DMODEL];
// attention partials
__device__ float g_pm[BATCH*NHEAD*UTOP*KSPLIT];
__device__ float g_ps[BATCH*NHEAD*UTOP*KSPLIT];
__device__ float g_pa[BATCH*NHEAD*UTOP*KSPLIT*DHEAD];

// ================= helpers =================
#define CP_ASYNC16(dst, src) \
    asm volatile("cp.async.cg.shared.global [%0], [%1], 16;" :: "r"(dst), "l"(src))
#define CP_COMMIT() asm volatile("cp.async.commit_group;" ::: "memory")

__device__ __forceinline__ uint32_t smem_u32(const void* p) {
    uint32_t a;
    asm("{ .reg .u64 t; cvta.to.shared.u64 t, %1; cvt.u32.u64 %0, t; }" : "=r"(a) : "l"(p));
    return a;
}
__device__ __forceinline__ void mma16816(float* c, const uint32_t* a, const uint32_t* b) {
    asm volatile("mma.sync.aligned.m16n8k16.row.col.f32.bf16.bf16.f32 "
        "{%0,%1,%2,%3}, {%4,%5,%6,%7}, {%8,%9}, {%0,%1,%2,%3};"
        : "+f"(c[0]), "+f"(c[1]), "+f"(c[2]), "+f"(c[3])
        : "r"(a[0]), "r"(a[1]), "r"(a[2]), "r"(a[3]), "r"(b[0]), "r"(b[1]));
}

// ================= split conversion =================
__global__ void splitk(const float* __restrict__ src, __nv_bfloat16* __restrict__ hi,
                       __nv_bfloat16* __restrict__ lo, int n)
{
    int i = blockIdx.x * blockDim.x + threadIdx.x;
    if (i < n) {
        float v = src[i];
        __nv_bfloat16 h = __float2bfloat16(v);
        hi[i] = h;
        lo[i] = __float2bfloat16(v - __bfloat162float(h));
    }
}
__global__ void splitk_ctx()
{
    int i = blockIdx.x * blockDim.x + threadIdx.x;
    float v = g_context[i];
    __nv_bfloat16 h = __float2bfloat16(v);
    g_chi[i] = h;
    g_clo[i] = __float2bfloat16(v - __bfloat162float(h));
}

// ================= tensor-core GEMM (mma.sync bf16, hi/lo 3-pass) =================
// C[m,n] = sum_k A[m,k]*B[n,k] + bias[n].
// CTA tile 128x128, 8 warps in 4x2 (M x N), warp tile 32x64.
// K-chunk 64, cp.async double buffer.
// SMEM tile layout: 128 rows x 64 bf16, row stride 144 bytes (16B pad -> <=2-way conflicts).
#define ROWB 144
#define TILE_B (128*ROWB)            // 18432
#define STAGE_B (4*TILE_B)           // 73728: Ahi | Alo | Bhi | Blo
#define GSMEM_TOTAL (2*STAGE_B)      // 147456
#define NCHUNK 16                    // K=1024 / 64

__device__ __forceinline__ uint32_t lds_u32(const char* base, int row, int kelem) {
    return *(const uint32_t*)(base + row*ROWB + kelem*2);
}

__device__ __forceinline__ void g_load_chunk(
    uint32_t stage, const __nv_bfloat16* Ahi, const __nv_bfloat16* Alo,
    const __nv_bfloat16* Bhi, const __nv_bfloat16* Blo,
    int m0, int n0, int kc, int t)
{
    int kb = kc * 128;   // byte offset into 2048B gmem row
    #pragma unroll
    for (int r = 0; r < 4; r++) {
        int j   = t + r * 256;
        int row = j >> 3;
        int cb  = j & 7;
        uint32_t dsto = (uint32_t)row * ROWB + cb * 16;
        const char* pa = (const char*)(Ahi + (size_t)(m0 + row) * DMODEL) + kb + cb * 16;
        const char* pb = (const char*)(Alo + (size_t)(m0 + row) * DMODEL) + kb + cb * 16;
        const char* pc = (const char*)(Bhi + (size_t)(n0 + row) * DMODEL) + kb + cb * 16;
        const char* pd = (const char*)(Blo + (size_t)(n0 + row) * DMODEL) + kb + cb * 16;
        CP_ASYNC16(stage + 0*TILE_B + dsto, pa);
        CP_ASYNC16(stage + 1*TILE_B + dsto, pb);
        CP_ASYNC16(stage + 2*TILE_B + dsto, pc);
        CP_ASYNC16(stage + 3*TILE_B + dsto, pd);
    }
}

// MODE 0: A = x split, B = [Wq;Wkv] split (N=3072), epilogue remap -> g_Q/g_K/g_V.
// MODE 1: A = ctx split, B = Wout split (N=1024), epilogue -> out.
template<int MODE>
__global__ void __launch_bounds__(256, 1) gemm_tc(
    const float* __restrict__ bias0, const float* __restrict__ bias1, float* __restrict__ out)
{
    extern __shared__ char smem[];
    uint32_t sb = smem_u32(smem);
    const int t = threadIdx.x;
    const int wid = t >> 5;
    const int lane = t & 31;
    const int g  = lane >> 2;     // group 0..7
    const int tg = lane & 3;      // 0..3
    const int wm = wid >> 1;      // 0..3
    const int wn = wid & 1;       // 0..1
    const int m0 = blockIdx.y * 128;
    const int n0 = blockIdx.x * 128;

    const __nv_bfloat16 *Ahi, *Alo, *Bhi, *Blo;
    if (MODE == 0) { Ahi = g_xhi; Alo = g_xlo; Bhi = g_whi;  Blo = g_wlo;  }
    else           { Ahi = g_chi; Alo = g_clo; Bhi = g_wohi; Blo = g_wolo; }

    float c[2][8][4];
    #pragma unroll
    for (int i = 0; i < 2; i++)
        #pragma unroll
        for (int j = 0; j < 8; j++)
            #pragma unroll
            for (int q = 0; q < 4; q++) c[i][j][q] = 0.f;

    g_load_chunk(sb, Ahi, Alo, Bhi, Blo, m0, n0, 0, t);
    CP_COMMIT();

    for (int kc = 0; kc < NCHUNK; kc++) {
        int buf = kc & 1;
        if (kc + 1 < NCHUNK) {
            g_load_chunk(sb + (buf ^ 1) * STAGE_B, Ahi, Alo, Bhi, Blo, m0, n0, kc + 1, t);
            CP_COMMIT();
            asm volatile("cp.async.wait_group 1;" ::: "memory");
        } else {
            asm volatile("cp.async.wait_group 0;" ::: "memory");
        }
        __syncthreads();

        const char* Ah = smem + buf * STAGE_B + 0*TILE_B;
        const char* Al = smem + buf * STAGE_B + 1*TILE_B;
        const char* Bh = smem + buf * STAGE_B + 2*TILE_B;
        const char* Bl = smem + buf * STAGE_B + 3*TILE_B;

        #pragma unroll
        for (int ks = 0; ks < 4; ks++) {
            int k0 = ks * 16;
            uint32_t ah[2][4], al[2][4];
            #pragma unroll
            for (int i = 0; i < 2; i++) {
                int r = wm * 32 + i * 16;
                ah[i][0] = lds_u32(Ah, r + g,     k0 + 2*tg);
                ah[i][1] = lds_u32(Ah, r + g + 8, k0 + 2*tg);
                ah[i][2] = lds_u32(Ah, r + g,     k0 + 2*tg + 8);
                ah[i][3] = lds_u32(Ah, r + g + 8, k0 + 2*tg + 8);
                al[i][0] = lds_u32(Al, r + g,     k0 + 2*tg);
                al[i][1] = lds_u32(Al, r + g + 8, k0 + 2*tg);
                al[i][2] = lds_u32(Al, r + g,     k0 + 2*tg + 8);
                al[i][3] = lds_u32(Al, r + g + 8, k0 + 2*tg + 8);
            }
            #pragma unroll
            for (int j = 0; j < 8; j++) {
                int nr = wn * 64 + j * 8;
                uint32_t bh[2], bl[2];
                bh[0] = lds_u32(Bh, nr + g, k0 + 2*tg);
                bh[1] = lds_u32(Bh, nr + g, k0 + 2*tg + 8);
                bl[0] = lds_u32(Bl, nr + g, k0 + 2*tg);
                bl[1] = lds_u32(Bl, nr + g, k0 + 2*tg + 8);
                #pragma unroll
                for (int i = 0; i < 2; i++) {
                    mma16816(c[i][j], ah[i], bh);
                    mma16816(c[i][j], ah[i], bl);
                    mma16816(c[i][j], al[i], bh);
                }
            }
        }
        __syncthreads();
    }

    // epilogue
    #pragma unroll
    for (int i = 0; i < 2; i++) {
        #pragma unroll
        for (int j = 0; j < 8; j++) {
            #pragma unroll
            for (int half = 0; half < 2; half++) {
                int m = m0 + wm * 32 + i * 16 + g + half * 8;
                int n = n0 + wn * 64 + j * 8 + 2 * tg;
                float v0 = c[i][j][half*2 + 0];
                float v1 = c[i][j][half*2 + 1];
                if (MODE == 0) {
                    int b_ = m >> 11, l = m & (LSEQ - 1);
                    int which = n >> 10;
                    int nloc  = n & 1023;
                    int h = nloc >> 6, dh = nloc & 63;
                    const float* bias = (n < DMODEL) ? (bias0 + n) : (bias1 + n - DMODEL);
                    float* dst = (which == 0 ? g_Q : which == 1 ? g_K : g_V)
                               + (((size_t)(b_ * NHEAD + h)) * LSEQ + l) * DHEAD + dh;
                    float2 w = make_float2(v0 + bias[0], v1 + bias[1]);
                    *(float2*)dst = w;
                } else {
                    float2 w = make_float2(v0 + bias0[n], v1 + bias0[n + 1]);
                    *(float2*)(out + (size_t)m * DMODEL + n) = w;
                }
            }
        }
    }
}

// ================= M scores =================
__global__ void score_m_kernel(const int* __restrict__ idxs)
{
    int warp = (blockIdx.x * blockDim.x + threadIdx.x) >> 5;
    int lane = threadIdx.x & 31;
    if (warp >= BHL) return;
    int l  = warp % LSEQ;
    int bh = warp / LSEQ;
    const float* qr = g_Q + (size_t)warp * DHEAD;
    float q0 = qr[lane], q1 = qr[lane + 32];
    float mx = -1e30f, sm = 0.f;
    #pragma unroll 4
    for (int u = 0; u < UTOP; u++) {
        int ki = idxs[l*UTOP + u];
        const float* kr = g_K + ((size_t)bh*LSEQ + ki)*DHEAD;
        float s = q0*kr[lane] + q1*kr[lane + 32];
        #pragma unroll
        for (int o = 16; o; o >>= 1) s += __shfl_xor_sync(0xffffffffu, s, o);
        mx = fmaxf(mx, s);
        sm += s;
    }
    if (lane == 0) g_M[warp] = mx - sm * (1.0f / UTOP);
}

// ================= top-U (shuffle-based) =================
__global__ void topk_kernel()
{
    int bh = blockIdx.x;
    __shared__ float vals[LSEQ];
    __shared__ float wv[8];
    __shared__ int   wi[8];
    int t = threadIdx.x, lane = t & 31, wid = t >> 5;
    for (int i = t; i < LSEQ; i += 256) vals[i] = g_M[(size_t)bh*LSEQ + i];
    __syncthreads();
    for (int it = 0; it < UTOP; it++) {
        float v = -2e30f; int bi = 0;
        int base = t * 8;
        #pragma unroll
        for (int j = 0; j < 8; j++) {
            float x = vals[base + j];
            if (x > v) { v = x; bi = base + j; }
        }
        #pragma unroll
        for (int o = 16; o; o >>= 1) {
            float ov = __shfl_xor_sync(0xffffffffu, v, o);
            int   oi = __shfl_xor_sync(0xffffffffu, bi, o);
            if (ov > v) { v = ov; bi = oi; }
        }
        if (lane == 0) { wv[wid] = v; wi[wid] = bi; }
        __syncthreads();
        if (t < 32) {
            float v2 = (t < 8) ? wv[t] : -2e30f;
            int   i2 = (t < 8) ? wi[t] : 0;
            #pragma unroll
            for (int o = 4; o; o >>= 1) {
                float ov = __shfl_xor_sync(0xffffffffu, v2, o);
                int   oi = __shfl_xor_sync(0xffffffffu, i2, o);
                if (ov > v2) { v2 = ov; i2 = oi; }
            }
            if (t == 0) { g_top[bh*UTOP + it] = i2; vals[i2] = -1e30f; }
        }
        __syncthreads();
    }
}

// ================= V mean =================
__global__ void vmean_part()      // grid (KSPLIT, BH), block 64
{
    int p = blockIdx.x, bh = blockIdx.y, dh = threadIdx.x;
    float s = 0.f;
    const float* base = g_V + ((size_t)bh*LSEQ + p*KS_KEYS)*DHEAD + dh;
    #pragma unroll 4
    for (int j = 0; j < KS_KEYS; j++) s += base[(size_t)j*DHEAD];
    g_vpart[((size_t)bh*KSPLIT + p)*DHEAD + dh] = s;
}
__global__ void vmean_fin()       // grid BH, block 64
{
    int bh = blockIdx.x, dh = threadIdx.x;
    float s = 0.f;
    #pragma unroll
    for (int p = 0; p < KSPLIT; p++) s += g_vpart[((size_t)bh*KSPLIT + p)*DHEAD + dh];
    g_vmean[bh*DHEAD + dh] = s * (1.0f / LSEQ);
}
__global__ void fill_ctx_kernel()
{
    int idx = blockIdx.x * blockDim.x + threadIdx.x;
    int dh = idx & 63;
    int h  = (idx >> 6) & 15;
    int bl = idx >> 10;
    int b_ = bl >> 11;
    g_context[idx] = g_vmean[(b_*NHEAD + h)*DHEAD + dh];
}

// ================= flash-split attention =================
// grid (KSPLIT, BH), block 256. Each block: 256 keys, all 40 selected queries.
__global__ void attn_flash()
{
    extern __shared__ float sm[];
    float* Qt   = sm;                        // [40][64]
    float* P    = sm + UTOP*DHEAD;           // [40][256]
    float* mrow = P + UTOP*KS_KEYS;          // [40]
    float* srow = mrow + UTOP;               // [40]
    int ks = blockIdx.x, bh = blockIdx.y;
    int t = threadIdx.x, lane = t & 31, wid = t >> 5;

    for (int i = t; i < UTOP*DHEAD; i += 256) {
        int u = i >> 6, d = i & 63;
        Qt[i] = g_Q[((size_t)bh*LSEQ + g_top[bh*UTOP + u])*DHEAD + d];
    }
    __syncthreads();

    int k = ks * KS_KEYS + t;
    const float4* Kr = (const float4*)(g_K + ((size_t)bh*LSEQ + k)*DHEAD);
    float S[UTOP];
    #pragma unroll
    for (int u = 0; u < UTOP; u++) S[u] = 0.f;
    #pragma unroll
    for (int c = 0; c < 16; c++) {
        float4 kv = Kr[c];
        #pragma unroll
        for (int u = 0; u < UTOP; u++) {
            float4 qv = *(const float4*)(Qt + u*DHEAD + c*4);
            S[u] += kv.x*qv.x + kv.y*qv.y + kv.z*qv.z + kv.w*qv.w;
        }
    }
    #pragma unroll
    for (int u = 0; u < UTOP; u++) P[u*KS_KEYS + t] = S[u] * 0.125f;
    __syncthreads();

    for (int i = 0; i < 5; i++) {
        int u = wid + i*8;
        float* row = P + u*KS_KEYS;
        float m = -1e30f;
        #pragma unroll
        for (int j = 0; j < 8; j++) m = fmaxf(m, row[lane + 32*j]);
        #pragma unroll
        for (int o = 16; o; o >>= 1) m = fmaxf(m, __shfl_xor_sync(0xffffffffu, m, o));
        float s = 0.f;
        #pragma unroll
        for (int j = 0; j < 8; j++) {
            float e = __expf(row[lane + 32*j] - m);
            row[lane + 32*j] = e;
            s += e;
        }
        #pragma unroll
        for (int o = 16; o; o >>= 1) s += __shfl_xor_sync(0xffffffffu, s, o);
        if (lane == 0) { mrow[u] = m; srow[u] = s; }
    }
    __syncthreads();

    int d = t & 63, ug = t >> 6;
    float acc[10];
    #pragma unroll
    for (int i = 0; i < 10; i++) acc[i] = 0.f;
    const float* Vb = g_V + ((size_t)bh*LSEQ + ks*KS_KEYS)*DHEAD + d;
    for (int kc = 0; kc < KS_KEYS/4; kc++) {
        float v0 = Vb[(size_t)(kc*4+0)*DHEAD];
        float v1 = Vb[(size_t)(kc*4+1)*DHEAD];
        float v2 = Vb[(size_t)(kc*4+2)*DHEAD];
        float v3 = Vb[(size_t)(kc*4+3)*DHEAD];
        #pragma unroll
        for (int i = 0; i < 10; i++) {
            int u = ug*10 + i;
            float4 p4 = *(const float4*)(P + u*KS_KEYS + kc*4);
            acc[i] += p4.x*v0 + p4.y*v1 + p4.z*v2 + p4.w*v3;
        }
    }
    #pragma unroll
    for (int i = 0; i < 10; i++) {
        int u = ug*10 + i;
        g_pa[(((size_t)(bh*UTOP + u))*KSPLIT + ks)*DHEAD + d] = acc[i];
    }
    if (t < UTOP) {
        g_pm[(bh*UTOP + t)*KSPLIT + ks] = mrow[t];
        g_ps[(bh*UTOP + t)*KSPLIT + ks] = srow[t];
    }
}

__global__ void attn_combine()    // grid BH*UTOP, block 64
{
    int bhu = blockIdx.x;
    int d = threadIdx.x;
    float m = -1e30f;
    #pragma unroll
    for (int j = 0; j < KSPLIT; j++) m = fmaxf(m, g_pm[bhu*KSPLIT + j]);
    float s = 0.f, a = 0.f;
    #pragma unroll
    for (int j = 0; j < KSPLIT; j++) {
        float w = __expf(g_pm[bhu*KSPLIT + j] - m);
        s += w * g_ps[bhu*KSPLIT + j];
        a += w * g_pa[((size_t)bhu*KSPLIT + j)*DHEAD + d];
    }
    g_ctx[(size_t)bhu*DHEAD + d] = a / s;
}

__global__ void scatter_kernel()
{
    int idx = blockIdx.x * blockDim.x + threadIdx.x;   // B*H*U*64
    int dh = idx & 63;
    int u  = (idx >> 6) % UTOP;
    int bh = idx / (UTOP * 64);
    int b_ = bh / NHEAD, h = bh % NHEAD;
    int l  = g_top[bh*UTOP + u];
    g_context[(((size_t)(b_*LSEQ + l))*NHEAD + h)*DHEAD + dh] = g_ctx[idx];
}

// -----------------------------------------------------------------------------
extern "C" void kernel_launch(void* const* d_in, const int* in_sizes, int n_in,
                              void* d_out, int out_size)
{
    const float* x    = (const float*)d_in[0];
    const float* Wq   = (const float*)d_in[1];
    const float* bq   = (const float*)d_in[2];
    const float* Wkv  = (const float*)d_in[3];
    const float* bkv  = (const float*)d_in[4];
    const float* Wout = (const float*)d_in[5];
    const float* bout = (const float*)d_in[6];
    const int*   idxs = (const int*)d_in[7];
    float* out = (float*)d_out;

    cudaFuncSetAttribute(gemm_tc<0>, cudaFuncAttributeMaxDynamicSharedMemorySize, GSMEM_TOTAL);
    cudaFuncSetAttribute(gemm_tc<1>, cudaFuncAttributeMaxDynamicSharedMemorySize, GSMEM_TOTAL);
    int attn_smem = (UTOP*DHEAD + UTOP*KS_KEYS + 2*UTOP) * sizeof(float);
    cudaFuncSetAttribute(attn_flash, cudaFuncAttributeMaxDynamicSharedMemorySize, attn_smem);

    __nv_bfloat16 *xhi, *xlo, *whi, *wlo, *wohi, *wolo;
    cudaGetSymbolAddress((void**)&xhi,  g_xhi);
    cudaGetSymbolAddress((void**)&xlo,  g_xlo);
    cudaGetSymbolAddress((void**)&whi,  g_whi);
    cudaGetSymbolAddress((void**)&wlo,  g_wlo);
    cudaGetSymbolAddress((void**)&wohi, g_wohi);
    cudaGetSymbolAddress((void**)&wolo, g_wolo);

    // split inputs/weights to bf16 hi/lo
    splitk<<<MROWS*DMODEL/256, 256>>>(x, xhi, xlo, MROWS*DMODEL);
    splitk<<<DMODEL*DMODEL/256, 256>>>(Wq, whi, wlo, DMODEL*DMODEL);
    splitk<<<2*DMODEL*DMODEL/256, 256>>>(Wkv, whi + DMODEL*DMODEL, wlo + DMODEL*DMODEL, 2*DMODEL*DMODEL);
    splitk<<<DMODEL*DMODEL/256, 256>>>(Wout, wohi, wolo, DMODEL*DMODEL);

    // fused QKV projection -> g_Q/g_K/g_V
    gemm_tc<0><<<dim3(3*DMODEL/128, MROWS/128), 256, GSMEM_TOTAL>>>(bq, bkv, nullptr);
    // sparsity measure + selection
    score_m_kernel<<<BHL/8, 256>>>(idxs);
    topk_kernel<<<BATCH*NHEAD, 256>>>();
    // V mean + context fill
    vmean_part<<<dim3(KSPLIT, BATCH*NHEAD), 64>>>();
    vmean_fin<<<BATCH*NHEAD, 64>>>();
    fill_ctx_kernel<<<(BATCH*LSEQ*DMODEL)/256, 256>>>();
    // flash-split attention over selected queries
    attn_flash<<<dim3(KSPLIT, BATCH*NHEAD), 256, attn_smem>>>();
    attn_combine<<<BATCH*NHEAD*UTOP, 64>>>();
    scatter_kernel<<<(BATCH*NHEAD*UTOP*DHEAD)/256, 256>>>();
    // output projection
    splitk_ctx<<<MROWS*DMODEL/256, 256>>>();
    gemm_tc<1><<<dim3(DMODEL/128, MROWS/128), 256, GSMEM_TOTAL>>>(bout, nullptr, out);
}

// round 4
// speedup vs baseline: 2.8153x; 1.0831x over previous
#include <cuda_runtime.h>
#include <cuda_bf16.h>
#include <cstdint>
#include <math.h>

#define BATCH 2
#define LSEQ 2048
#define DMODEL 1024
#define NHEAD 16
#define DHEAD 64
#define UTOP 40
#define MROWS (BATCH*LSEQ)          // 4096
#define BHL (BATCH*NHEAD*LSEQ)      // 65536
#define KSPLIT 8
#define KS_KEYS (LSEQ/KSPLIT)       // 256
#define MODROWS 640                 // padded modified-row count per batch (>= 40*16 max)

// ---------------- scratch (static device globals; no allocation) -------------
__device__ float g_Q[BATCH*NHEAD*LSEQ*DHEAD];
__device__ float g_K[BATCH*NHEAD*LSEQ*DHEAD];
__device__ float g_V[BATCH*NHEAD*LSEQ*DHEAD];
__device__ float g_M[BHL];
__device__ int   g_top[BATCH*NHEAD*UTOP];
__device__ float g_ctx[BATCH*NHEAD*UTOP*DHEAD];
__device__ float g_vpart[BATCH*NHEAD*KSPLIT*DHEAD];
__device__ float g_vmean[BATCH*NHEAD*DHEAD];    // == base_ctx[b][k], k=h*64+dh
// bf16 split operands
__device__ __nv_bfloat16 g_xhi[MROWS*DMODEL], g_xlo[MROWS*DMODEL];
__device__ __nv_bfloat16 g_whi[3*DMODEL*DMODEL], g_wlo[3*DMODEL*DMODEL];   // [Wq;Wkv]
__device__ __nv_bfloat16 g_wohi[DMODEL*DMODEL], g_wolo[DMODEL*DMODEL];
__device__ __nv_bfloat16 g_cmhi[BATCH*MODROWS*DMODEL], g_cmlo[BATCH*MODROWS*DMODEL];
// attention partials
__device__ float g_pm[BATCH*NHEAD*UTOP*KSPLIT];
__device__ float g_ps[BATCH*NHEAD*UTOP*KSPLIT];
__device__ float g_pa[BATCH*NHEAD*UTOP*KSPLIT*DHEAD];
// output-projection compaction
__device__ unsigned char g_selu[BATCH*NHEAD*LSEQ];   // u+1 or 0
__device__ int   g_flags[BATCH*LSEQ];
__device__ int   g_rowlist[BATCH*MODROWS];
__device__ float g_baseout[BATCH*DMODEL];

// ================= helpers =================
#define CP_ASYNC16(dst, src) \
    asm volatile("cp.async.cg.shared.global [%0], [%1], 16;" :: "r"(dst), "l"(src))
#define CP_COMMIT() asm volatile("cp.async.commit_group;" ::: "memory")

__device__ __forceinline__ uint32_t smem_u32(const void* p) {
    uint32_t a;
    asm("{ .reg .u64 t; cvta.to.shared.u64 t, %1; cvt.u32.u64 %0, t; }" : "=r"(a) : "l"(p));
    return a;
}
__device__ __forceinline__ void mma16816(float* c, const uint32_t* a, const uint32_t* b) {
    asm volatile("mma.sync.aligned.m16n8k16.row.col.f32.bf16.bf16.f32 "
        "{%0,%1,%2,%3}, {%4,%5,%6,%7}, {%8,%9}, {%0,%1,%2,%3};"
        : "+f"(c[0]), "+f"(c[1]), "+f"(c[2]), "+f"(c[3])
        : "r"(a[0]), "r"(a[1]), "r"(a[2]), "r"(a[3]), "r"(b[0]), "r"(b[1]));
}
__device__ __forceinline__ void ldsm_x4(uint32_t* r, uint32_t addr) {
    asm volatile("ldmatrix.sync.aligned.m8n8.x4.shared.b16 {%0,%1,%2,%3}, [%4];"
        : "=r"(r[0]), "=r"(r[1]), "=r"(r[2]), "=r"(r[3]) : "r"(addr));
}

// ================= split conversion =================
__global__ void splitk(const float* __restrict__ src, __nv_bfloat16* __restrict__ hi,
                       __nv_bfloat16* __restrict__ lo, int n)
{
    int i = blockIdx.x * blockDim.x + threadIdx.x;
    if (i < n) {
        float v = src[i];
        __nv_bfloat16 h = __float2bfloat16(v);
        hi[i] = h;
        lo[i] = __float2bfloat16(v - __bfloat162float(h));
    }
}

// ================= tensor-core GEMM (mma.sync bf16, hi/lo 3-pass, ldmatrix) ====
// C[m,n] = sum_k A[m,k]*B[n,k] + bias[n].
// CTA tile 128x128, 8 warps 4x2, warp tile 32x64, K-chunk 64, double buffer.
// SMEM rows: 64 bf16, stride 144B (conflict-free for LDSM phases).
#define ROWB 144
#define TILE_B (128*ROWB)            // 18432
#define STAGE_B (4*TILE_B)           // 73728: Ahi | Alo | Bhi | Blo
#define GSMEM_TOTAL (2*STAGE_B)      // 147456
#define NCHUNK 16                    // K=1024 / 64

__device__ __forceinline__ void g_load_chunk(
    uint32_t stage, const __nv_bfloat16* Ahi, const __nv_bfloat16* Alo,
    const __nv_bfloat16* Bhi, const __nv_bfloat16* Blo,
    int m0, int n0, int kc, int t)
{
    int kb = kc * 128;   // byte offset into 2048B gmem row
    #pragma unroll
    for (int r = 0; r < 4; r++) {
        int j   = t + r * 256;
        int row = j >> 3;
        int cb  = j & 7;
        uint32_t dsto = (uint32_t)row * ROWB + cb * 16;
        const char* pa = (const char*)(Ahi + (size_t)(m0 + row) * DMODEL) + kb + cb * 16;
        const char* pb = (const char*)(Alo + (size_t)(m0 + row) * DMODEL) + kb + cb * 16;
        const char* pc = (const char*)(Bhi + (size_t)(n0 + row) * DMODEL) + kb + cb * 16;
        const char* pd = (const char*)(Blo + (size_t)(n0 + row) * DMODEL) + kb + cb * 16;
        CP_ASYNC16(stage + 0*TILE_B + dsto, pa);
        CP_ASYNC16(stage + 1*TILE_B + dsto, pb);
        CP_ASYNC16(stage + 2*TILE_B + dsto, pc);
        CP_ASYNC16(stage + 3*TILE_B + dsto, pd);
    }
}

// MODE 0: A = x split, B = [Wq;Wkv] split (N=3072), epilogue remap -> g_Q/g_K/g_V.
// MODE 1: A = Cmod split (2*640 rows), B = Wout split, epilogue scatter rows -> out.
template<int MODE>
__global__ void __launch_bounds__(256, 1) gemm_tc(
    const float* __restrict__ bias0, const float* __restrict__ bias1, float* __restrict__ out)
{
    extern __shared__ char smem[];
    uint32_t sb = smem_u32(smem);
    const int t = threadIdx.x;
    const int wid = t >> 5;
    const int lane = t & 31;
    const int g  = lane >> 2;
    const int tg = lane & 3;
    const int wm = wid >> 1;      // 0..3
    const int wn = wid & 1;       // 0..1
    const int m0 = blockIdx.y * 128;
    const int n0 = blockIdx.x * 128;

    const __nv_bfloat16 *Ahi, *Alo, *Bhi, *Blo;
    if (MODE == 0) { Ahi = g_xhi; Alo = g_xlo; Bhi = g_whi;  Blo = g_wlo;  }
    else           { Ahi = g_cmhi; Alo = g_cmlo; Bhi = g_wohi; Blo = g_wolo; }

    // ldmatrix per-lane intra-tile offsets
    const uint32_t aoff = (uint32_t)(lane & 15) * ROWB + ((lane >> 4) & 1) * 16;
    const uint32_t boff = (uint32_t)((lane & 7) + ((lane >> 4) & 1) * 8) * ROWB
                        + ((lane >> 3) & 1) * 16;

    float c[2][8][4];
    #pragma unroll
    for (int i = 0; i < 2; i++)
        #pragma unroll
        for (int j = 0; j < 8; j++)
            #pragma unroll
            for (int q = 0; q < 4; q++) c[i][j][q] = 0.f;

    g_load_chunk(sb, Ahi, Alo, Bhi, Blo, m0, n0, 0, t);
    CP_COMMIT();

    for (int kc = 0; kc < NCHUNK; kc++) {
        int buf = kc & 1;
        if (kc + 1 < NCHUNK) {
            g_load_chunk(sb + (buf ^ 1) * STAGE_B, Ahi, Alo, Bhi, Blo, m0, n0, kc + 1, t);
            CP_COMMIT();
            asm volatile("cp.async.wait_group 1;" ::: "memory");
        } else {
            asm volatile("cp.async.wait_group 0;" ::: "memory");
        }
        __syncthreads();

        uint32_t Ah = sb + buf * STAGE_B + 0*TILE_B;
        uint32_t Al = sb + buf * STAGE_B + 1*TILE_B;
        uint32_t Bh = sb + buf * STAGE_B + 2*TILE_B;
        uint32_t Bl = sb + buf * STAGE_B + 3*TILE_B;

        #pragma unroll
        for (int ks = 0; ks < 4; ks++) {
            uint32_t kcol = ks * 32;
            uint32_t ah[2][4], al[2][4];
            #pragma unroll
            for (int i = 0; i < 2; i++) {
                uint32_t rbase = (uint32_t)(wm * 32 + i * 16) * ROWB + kcol;
                ldsm_x4(ah[i], Ah + rbase + aoff);
                ldsm_x4(al[i], Al + rbase + aoff);
            }
            #pragma unroll
            for (int jj = 0; jj < 4; jj++) {
                uint32_t nbase = (uint32_t)(wn * 64 + jj * 16) * ROWB + kcol;
                uint32_t bh[4], bl[4];
                ldsm_x4(bh, Bh + nbase + boff);
                ldsm_x4(bl, Bl + nbase + boff);
                #pragma unroll
                for (int i = 0; i < 2; i++) {
                    mma16816(c[i][2*jj],   ah[i], bh);
                    mma16816(c[i][2*jj],   ah[i], bl);
                    mma16816(c[i][2*jj],   al[i], bh);
                    mma16816(c[i][2*jj+1], ah[i], bh + 2);
                    mma16816(c[i][2*jj+1], ah[i], bl + 2);
                    mma16816(c[i][2*jj+1], al[i], bh + 2);
                }
            }
        }
        __syncthreads();
    }

    // epilogue
    #pragma unroll
    for (int i = 0; i < 2; i++) {
        #pragma unroll
        for (int j = 0; j < 8; j++) {
            #pragma unroll
            for (int half = 0; half < 2; half++) {
                int m = m0 + wm * 32 + i * 16 + g + half * 8;
                int n = n0 + wn * 64 + j * 8 + 2 * tg;
                float v0 = c[i][j][half*2 + 0];
                float v1 = c[i][j][half*2 + 1];
                if (MODE == 0) {
                    int b_ = m >> 11, l = m & (LSEQ - 1);
                    int which = n >> 10;
                    int nloc  = n & 1023;
                    int h = nloc >> 6, dh = nloc & 63;
                    const float* bias = (n < DMODEL) ? (bias0 + n) : (bias1 + n - DMODEL);
                    float* dst = (which == 0 ? g_Q : which == 1 ? g_K : g_V)
                               + (((size_t)(b_ * NHEAD + h)) * LSEQ + l) * DHEAD + dh;
                    float2 w = make_float2(v0 + bias[0], v1 + bias[1]);
                    *(float2*)dst = w;
                } else {
                    int b_ = m / MODROWS;
                    int i_ = m - b_ * MODROWS;
                    int l  = g_rowlist[b_ * MODROWS + i_];
                    float2 w = make_float2(v0 + bias0[n], v1 + bias0[n + 1]);
                    *(float2*)(out + ((size_t)(b_ * LSEQ + l)) * DMODEL + n) = w;
                }
            }
        }
    }
}

// ================= M scores =================
__global__ void score_m_kernel(const int* __restrict__ idxs)
{
    int warp = (blockIdx.x * blockDim.x + threadIdx.x) >> 5;
    int lane = threadIdx.x & 31;
    if (warp >= BHL) return;
    int l  = warp % LSEQ;
    int bh = warp / LSEQ;
    const float* qr = g_Q + (size_t)warp * DHEAD;
    float q0 = qr[lane], q1 = qr[lane + 32];
    float mx = -1e30f, sm = 0.f;
    #pragma unroll 4
    for (int u = 0; u < UTOP; u++) {
        int ki = idxs[l*UTOP + u];
        const float* kr = g_K + ((size_t)bh*LSEQ + ki)*DHEAD;
        float s = q0*kr[lane] + q1*kr[lane + 32];
        #pragma unroll
        for (int o = 16; o; o >>= 1) s += __shfl_xor_sync(0xffffffffu, s, o);
        mx = fmaxf(mx, s);
        sm += s;
    }
    if (lane == 0) g_M[warp] = mx - sm * (1.0f / UTOP);
}

// ================= top-U (shuffle-based) =================
__global__ void topk_kernel()
{
    int bh = blockIdx.x;
    __shared__ float vals[LSEQ];
    __shared__ float wv[8];
    __shared__ int   wi[8];
    int t = threadIdx.x, lane = t & 31, wid = t >> 5;
    for (int i = t; i < LSEQ; i += 256) vals[i] = g_M[(size_t)bh*LSEQ + i];
    __syncthreads();
    for (int it = 0; it < UTOP; it++) {
        float v = -2e30f; int bi = 0;
        int base = t * 8;
        #pragma unroll
        for (int j = 0; j < 8; j++) {
            float x = vals[base + j];
            if (x > v) { v = x; bi = base + j; }
        }
        #pragma unroll
        for (int o = 16; o; o >>= 1) {
            float ov = __shfl_xor_sync(0xffffffffu, v, o);
            int   oi = __shfl_xor_sync(0xffffffffu, bi, o);
            if (ov > v) { v = ov; bi = oi; }
        }
        if (lane == 0) { wv[wid] = v; wi[wid] = bi; }
        __syncthreads();
        if (t < 32) {
            float v2 = (t < 8) ? wv[t] : -2e30f;
            int   i2 = (t < 8) ? wi[t] : 0;
            #pragma unroll
            for (int o = 4; o; o >>= 1) {
                float ov = __shfl_xor_sync(0xffffffffu, v2, o);
                int   oi = __shfl_xor_sync(0xffffffffu, i2, o);
                if (ov > v2) { v2 = ov; i2 = oi; }
            }
            if (t == 0) { g_top[bh*UTOP + it] = i2; vals[i2] = -1e30f; }
        }
        __syncthreads();
    }
}

// ================= V mean =================
__global__ void vmean_part()      // grid (KSPLIT, BH), block 64
{
    int p = blockIdx.x, bh = blockIdx.y, dh = threadIdx.x;
    float s = 0.f;
    const float* base = g_V + ((size_t)bh*LSEQ + p*KS_KEYS)*DHEAD + dh;
    #pragma unroll 4
    for (int j = 0; j < KS_KEYS; j++) s += base[(size_t)j*DHEAD];
    g_vpart[((size_t)bh*KSPLIT + p)*DHEAD + dh] = s;
}
__global__ void vmean_fin()       // grid BH, block 64
{
    int bh = blockIdx.x, dh = threadIdx.x;
    float s = 0.f;
    #pragma unroll
    for (int p = 0; p < KSPLIT; p++) s += g_vpart[((size_t)bh*KSPLIT + p)*DHEAD + dh];
    g_vmean[bh*DHEAD + dh] = s * (1.0f / LSEQ);
}

// ================= flash-split attention =================
__global__ void attn_flash()
{
    extern __shared__ float sm[];
    float* Qt   = sm;                        // [40][64]
    float* P    = sm + UTOP*DHEAD;           // [40][256]
    float* mrow = P + UTOP*KS_KEYS;          // [40]
    float* srow = mrow + UTOP;               // [40]
    int ks = blockIdx.x, bh = blockIdx.y;
    int t = threadIdx.x, lane = t & 31, wid = t >> 5;

    for (int i = t; i < UTOP*DHEAD; i += 256) {
        int u = i >> 6, d = i & 63;
        Qt[i] = g_Q[((size_t)bh*LSEQ + g_top[bh*UTOP + u])*DHEAD + d];
    }
    __syncthreads();

    int k = ks * KS_KEYS + t;
    const float4* Kr = (const float4*)(g_K + ((size_t)bh*LSEQ + k)*DHEAD);
    float S[UTOP];
    #pragma unroll
    for (int u = 0; u < UTOP; u++) S[u] = 0.f;
    #pragma unroll
    for (int c = 0; c < 16; c++) {
        float4 kv = Kr[c];
        #pragma unroll
        for (int u = 0; u < UTOP; u++) {
            float4 qv = *(const float4*)(Qt + u*DHEAD + c*4);
            S[u] += kv.x*qv.x + kv.y*qv.y + kv.z*qv.z + kv.w*qv.w;
        }
    }
    #pragma unroll
    for (int u = 0; u < UTOP; u++) P[u*KS_KEYS + t] = S[u] * 0.125f;
    __syncthreads();

    for (int i = 0; i < 5; i++) {
        int u = wid + i*8;
        float* row = P + u*KS_KEYS;
        float m = -1e30f;
        #pragma unroll
        for (int j = 0; j < 8; j++) m = fmaxf(m, row[lane + 32*j]);
        #pragma unroll
        for (int o = 16; o; o >>= 1) m = fmaxf(m, __shfl_xor_sync(0xffffffffu, m, o));
        float s = 0.f;
        #pragma unroll
        for (int j = 0; j < 8; j++) {
            float e = __expf(row[lane + 32*j] - m);
            row[lane + 32*j] = e;
            s += e;
        }
        #pragma unroll
        for (int o = 16; o; o >>= 1) s += __shfl_xor_sync(0xffffffffu, s, o);
        if (lane == 0) { mrow[u] = m; srow[u] = s; }
    }
    __syncthreads();

    int d = t & 63, ug = t >> 6;
    float acc[10];
    #pragma unroll
    for (int i = 0; i < 10; i++) acc[i] = 0.f;
    const float* Vb = g_V + ((size_t)bh*LSEQ + ks*KS_KEYS)*DHEAD + d;
    for (int kc = 0; kc < KS_KEYS/4; kc++) {
        float v0 = Vb[(size_t)(kc*4+0)*DHEAD];
        float v1 = Vb[(size_t)(kc*4+1)*DHEAD];
        float v2 = Vb[(size_t)(kc*4+2)*DHEAD];
        float v3 = Vb[(size_t)(kc*4+3)*DHEAD];
        #pragma unroll
        for (int i = 0; i < 10; i++) {
            int u = ug*10 + i;
            float4 p4 = *(const float4*)(P + u*KS_KEYS + kc*4);
            acc[i] += p4.x*v0 + p4.y*v1 + p4.z*v2 + p4.w*v3;
        }
    }
    #pragma unroll
    for (int i = 0; i < 10; i++) {
        int u = ug*10 + i;
        g_pa[(((size_t)(bh*UTOP + u))*KSPLIT + ks)*DHEAD + d] = acc[i];
    }
    if (t < UTOP) {
        g_pm[(bh*UTOP + t)*KSPLIT + ks] = mrow[t];
        g_ps[(bh*UTOP + t)*KSPLIT + ks] = srow[t];
    }
}

__global__ void attn_combine()    // grid BH*UTOP, block 64
{
    int bhu = blockIdx.x;
    int d = threadIdx.x;
    float m = -1e30f;
    #pragma unroll
    for (int j = 0; j < KSPLIT; j++) m = fmaxf(m, g_pm[bhu*KSPLIT + j]);
    float s = 0.f, a = 0.f;
    #pragma unroll
    for (int j = 0; j < KSPLIT; j++) {
        float w = __expf(g_pm[bhu*KSPLIT + j] - m);
        s += w * g_ps[bhu*KSPLIT + j];
        a += w * g_pa[((size_t)bhu*KSPLIT + j)*DHEAD + d];
    }
    g_ctx[(size_t)bhu*DHEAD + d] = a / s;
}

// ================= output-projection compaction =================
__global__ void sel_clear()       // grid 256, block 256 -> 65536 threads
{
    int i = blockIdx.x * blockDim.x + threadIdx.x;
    g_selu[i] = 0;
    if (i < BATCH*LSEQ) g_flags[i] = 0;
}
__global__ void sel_mark()        // grid BH, block UTOP
{
    int bh = blockIdx.x, u = threadIdx.x;
    int l = g_top[bh*UTOP + u];
    g_selu[bh*LSEQ + l] = (unsigned char)(u + 1);
    int b_ = bh / NHEAD;
    g_flags[b_*LSEQ + l] = 1;
}
__global__ void compact_kernel()  // grid BATCH, block 256
{
    int b = blockIdx.x, t = threadIdx.x;
    __shared__ int cnts[256];
    __shared__ int l0s;
    int mine[8];
    int cnt = 0;
    #pragma unroll
    for (int j = 0; j < 8; j++) {
        mine[j] = g_flags[b*LSEQ + t*8 + j];
        cnt += mine[j];
    }
    cnts[t] = cnt;
    __syncthreads();
    for (int off = 1; off < 256; off <<= 1) {
        int v = (t >= off) ? cnts[t - off] : 0;
        __syncthreads();
        cnts[t] += v;
        __syncthreads();
    }
    int pos = cnts[t] - cnt;
    int total = cnts[255];
    #pragma unroll
    for (int j = 0; j < 8; j++)
        if (mine[j]) g_rowlist[b*MODROWS + pos++] = t*8 + j;
    __syncthreads();
    if (t == 0) l0s = g_rowlist[b*MODROWS];
    __syncthreads();
    for (int i = total + t; i < MODROWS; i += 256) g_rowlist[b*MODROWS + i] = l0s;
}
// Cmod[b][i][d] hi/lo split: selected head -> ctx_update, else vmean
__global__ void build_cmod()      // grid (BATCH*MODROWS*DMODEL)/256
{
    int idx = blockIdx.x * blockDim.x + threadIdx.x;
    int d = idx & 1023;
    int r = (idx >> 10) % MODROWS;
    int b = idx / (MODROWS * 1024);
    int l = g_rowlist[b*MODROWS + r];
    int h = d >> 6;
    int bh = b * NHEAD + h;
    unsigned char u = g_selu[bh*LSEQ + l];
    float v = u ? g_ctx[((size_t)bh*UTOP + (u-1))*DHEAD + (d & 63)]
                : g_vmean[bh*DHEAD + (d & 63)];
    __nv_bfloat16 hi = __float2bfloat16(v);
    g_cmhi[idx] = hi;
    g_cmlo[idx] = __float2bfloat16(v - __bfloat162float(hi));
}
// base_out[b][n] = vmean_ctx[b] . Wout[n] + bout[n] (fp32 exact)
__global__ void base_out_kernel(const float* __restrict__ Wout, const float* __restrict__ bout)
{
    int gid = blockIdx.x * 8 + (threadIdx.x >> 5);   // warp id over 2048
    int lane = threadIdx.x & 31;
    int b = gid >> 10, n = gid & 1023;
    const float* w = Wout + (size_t)n * DMODEL;
    const float* cb = g_vmean + b * DMODEL;          // vmean layout == base_ctx
    float s = 0.f;
    #pragma unroll 8
    for (int k = lane; k < DMODEL; k += 32) s += cb[k] * w[k];
    #pragma unroll
    for (int o = 16; o; o >>= 1) s += __shfl_xor_sync(0xffffffffu, s, o);
    if (lane == 0) g_baseout[b*DMODEL + n] = s + bout[n];
}
__global__ void broadcast_base(float* __restrict__ out)   // 4096x1024 fill
{
    int idx = blockIdx.x * blockDim.x + threadIdx.x;
    int b = idx >> 21;
    out[idx] = g_baseout[b*DMODEL + (idx & 1023)];
}

// -----------------------------------------------------------------------------
extern "C" void kernel_launch(void* const* d_in, const int* in_sizes, int n_in,
                              void* d_out, int out_size)
{
    const float* x    = (const float*)d_in[0];
    const float* Wq   = (const float*)d_in[1];
    const float* bq   = (const float*)d_in[2];
    const float* Wkv  = (const float*)d_in[3];
    const float* bkv  = (const float*)d_in[4];
    const float* Wout = (const float*)d_in[5];
    const float* bout = (const float*)d_in[6];
    const int*   idxs = (const int*)d_in[7];
    float* out = (float*)d_out;

    cudaFuncSetAttribute(gemm_tc<0>, cudaFuncAttributeMaxDynamicSharedMemorySize, GSMEM_TOTAL);
    cudaFuncSetAttribute(gemm_tc<1>, cudaFuncAttributeMaxDynamicSharedMemorySize, GSMEM_TOTAL);
    int attn_smem = (UTOP*DHEAD + UTOP*KS_KEYS + 2*UTOP) * sizeof(float);
    cudaFuncSetAttribute(attn_flash, cudaFuncAttributeMaxDynamicSharedMemorySize, attn_smem);

    __nv_bfloat16 *xhi, *xlo, *whi, *wlo, *wohi, *wolo;
    cudaGetSymbolAddress((void**)&xhi,  g_xhi);
    cudaGetSymbolAddress((void**)&xlo,  g_xlo);
    cudaGetSymbolAddress((void**)&whi,  g_whi);
    cudaGetSymbolAddress((void**)&wlo,  g_wlo);
    cudaGetSymbolAddress((void**)&wohi, g_wohi);
    cudaGetSymbolAddress((void**)&wolo, g_wolo);

    // bf16 hi/lo splits
    splitk<<<MROWS*DMODEL/256, 256>>>(x, xhi, xlo, MROWS*DMODEL);
    splitk<<<DMODEL*DMODEL/256, 256>>>(Wq, whi, wlo, DMODEL*DMODEL);
    splitk<<<2*DMODEL*DMODEL/256, 256>>>(Wkv, whi + DMODEL*DMODEL, wlo + DMODEL*DMODEL, 2*DMODEL*DMODEL);
    splitk<<<DMODEL*DMODEL/256, 256>>>(Wout, wohi, wolo, DMODEL*DMODEL);

    // fused QKV projection -> g_Q/g_K/g_V
    gemm_tc<0><<<dim3(3*DMODEL/128, MROWS/128), 256, GSMEM_TOTAL>>>(bq, bkv, nullptr);
    // sparsity measure + selection
    score_m_kernel<<<BHL/8, 256>>>(idxs);
    topk_kernel<<<BATCH*NHEAD, 256>>>();
    // selection maps + compaction
    sel_clear<<<256, 256>>>();
    sel_mark<<<BATCH*NHEAD, UTOP>>>();
    compact_kernel<<<BATCH, 256>>>();
    // V mean
    vmean_part<<<dim3(KSPLIT, BATCH*NHEAD), 64>>>();
    vmean_fin<<<BATCH*NHEAD, 64>>>();
    // flash-split attention over selected queries
    attn_flash<<<dim3(KSPLIT, BATCH*NHEAD), 256, attn_smem>>>();
    attn_combine<<<BATCH*NHEAD*UTOP, 64>>>();
    // base output rows (exact fp32) + broadcast
    base_out_kernel<<<BATCH*DMODEL/8, 256>>>(Wout, bout);
    broadcast_base<<<MROWS*DMODEL/256, 256>>>(out);
    // modified context rows -> bf16 split -> scatter GEMM
    build_cmod<<<BATCH*MODROWS*DMODEL/256, 256>>>();
    gemm_tc<1><<<dim3(DMODEL/128, BATCH*MODROWS/128), 256, GSMEM_TOTAL>>>(bout, nullptr, out);
}

// round 6
// speedup vs baseline: 3.0832x; 1.0952x over previous
#include <cuda_runtime.h>
#include <cuda_bf16.h>
#include <cuda_fp16.h>
#include <cstdint>
#include <math.h>

#define BATCH 2
#define LSEQ 2048
#define DMODEL 1024
#define NHEAD 16
#define DHEAD 64
#define UTOP 40
#define MROWS (BATCH*LSEQ)          // 4096
#define BHL (BATCH*NHEAD*LSEQ)      // 65536
#define KSPLIT 8
#define KS_KEYS (LSEQ/KSPLIT)       // 256
#define MODROWS 640                 // padded modified-row count per batch
#define DD (DMODEL*DMODEL)          // 1048576

// ---------------- scratch (static device globals; no allocation) -------------
__device__ float g_Q[BATCH*NHEAD*LSEQ*DHEAD];
__device__ float g_K[BATCH*NHEAD*LSEQ*DHEAD];
__device__ float g_V[BATCH*NHEAD*LSEQ*DHEAD];
__device__ float g_M[BHL];
__device__ int   g_top[BATCH*NHEAD*UTOP];
__device__ float g_ctx[BATCH*NHEAD*UTOP*DHEAD];
__device__ float g_vpart[BATCH*NHEAD*KSPLIT*DHEAD];
__device__ float g_vmean[BATCH*NHEAD*DHEAD];
// operands: x in bf16 hi/lo (QK path) and fp16 hi/lo (V path)
__device__ __nv_bfloat16 g_xbh[MROWS*DMODEL], g_xbl[MROWS*DMODEL];
__device__ __half        g_xfh[MROWS*DMODEL], g_xfl[MROWS*DMODEL];
__device__ __nv_bfloat16 g_wbh[2*DD], g_wbl[2*DD];    // [Wq ; Wkv_K] bf16 hi/lo
__device__ __half        g_wv[DD];                    // Wkv_V fp16
__device__ __half        g_wo[DD];                    // Wout fp16
__device__ __half        g_cmh[BATCH*MODROWS*DMODEL], g_cml[BATCH*MODROWS*DMODEL];
// attention partials
__device__ float g_pm[BATCH*NHEAD*UTOP*KSPLIT];
__device__ float g_ps[BATCH*NHEAD*UTOP*KSPLIT];
__device__ float g_pa[BATCH*NHEAD*UTOP*KSPLIT*DHEAD];
// output-projection compaction
__device__ unsigned char g_selu[BATCH*NHEAD*LSEQ];
__device__ int   g_flags[BATCH*LSEQ];
__device__ int   g_rowlist[BATCH*MODROWS];
__device__ float g_baseout[BATCH*DMODEL];

// ================= helpers =================
#define CP_ASYNC16(dst, src) \
    asm volatile("cp.async.cg.shared.global [%0], [%1], 16;" :: "r"(dst), "l"(src))
#define CP_COMMIT() asm volatile("cp.async.commit_group;" ::: "memory")

__device__ __forceinline__ uint32_t smem_u32(const void* p) {
    uint32_t a;
    asm("{ .reg .u64 t; cvta.to.shared.u64 t, %1; cvt.u32.u64 %0, t; }" : "=r"(a) : "l"(p));
    return a;
}
__device__ __forceinline__ void mma_bf(float* c, const uint32_t* a, const uint32_t* b) {
    asm volatile("mma.sync.aligned.m16n8k16.row.col.f32.bf16.bf16.f32 "
        "{%0,%1,%2,%3}, {%4,%5,%6,%7}, {%8,%9}, {%0,%1,%2,%3};"
        : "+f"(c[0]), "+f"(c[1]), "+f"(c[2]), "+f"(c[3])
        : "r"(a[0]), "r"(a[1]), "r"(a[2]), "r"(a[3]), "r"(b[0]), "r"(b[1]));
}
__device__ __forceinline__ void mma_f16(float* c, const uint32_t* a, const uint32_t* b) {
    asm volatile("mma.sync.aligned.m16n8k16.row.col.f32.f16.f16.f32 "
        "{%0,%1,%2,%3}, {%4,%5,%6,%7}, {%8,%9}, {%0,%1,%2,%3};"
        : "+f"(c[0]), "+f"(c[1]), "+f"(c[2]), "+f"(c[3])
        : "r"(a[0]), "r"(a[1]), "r"(a[2]), "r"(a[3]), "r"(b[0]), "r"(b[1]));
}
__device__ __forceinline__ void ldsm_x4(uint32_t* r, uint32_t addr) {
    asm volatile("ldmatrix.sync.aligned.m8n8.x4.shared.b16 {%0,%1,%2,%3}, [%4];"
        : "=r"(r[0]), "=r"(r[1]), "=r"(r[2]), "=r"(r[3]) : "r"(addr));
}

// ================= conversions =================
// x -> bf16 hi/lo + fp16 hi/lo (4M threads)
__global__ void splitX(const float* __restrict__ src)
{
    int i = blockIdx.x * blockDim.x + threadIdx.x;
    float v = src[i];
    __nv_bfloat16 bh = __float2bfloat16(v);
    g_xbh[i] = bh;
    g_xbl[i] = __float2bfloat16(v - __bfloat162float(bh));
    __half fh = __float2half(v);
    g_xfh[i] = fh;
    g_xfl[i] = __float2half(v - __half2float(fh));
}
// [Wq ; Wkv_K] -> bf16 hi/lo (2M threads)
__global__ void splitWb(const float* __restrict__ Wq, const float* __restrict__ Wkv)
{
    int i = blockIdx.x * blockDim.x + threadIdx.x;
    float v = (i < DD) ? Wq[i] : Wkv[i - DD];
    __nv_bfloat16 h = __float2bfloat16(v);
    g_wbh[i] = h;
    g_wbl[i] = __float2bfloat16(v - __bfloat162float(h));
}
// Wkv_V, Wout -> fp16 (2M threads)
__global__ void convH(const float* __restrict__ Wkv, const float* __restrict__ Wout)
{
    int i = blockIdx.x * blockDim.x + threadIdx.x;
    if (i < DD) g_wv[i] = __float2half(Wkv[DD + i]);
    else        g_wo[i - DD] = __float2half(Wout[i - DD]);
}

// ================= tensor-core GEMM =================
// CTA tile 128x128, 8 warps 4x2, warp tile 32x64, K-chunk 32, double buffer,
// 2 CTAs/SM. Rows: 32 els (64B) + 16B pad = 80B stride (LDSM conflict-free).
// MODE 0: QK — A = x bf16 hi/lo, B = [Wq;WkvK] bf16 hi/lo, 3-pass. N=2048.
// MODE 1: V  — A = x fp16 hi/lo, B = WkvV fp16, 2-pass. N=1024.
// MODE 2: OUT— A = Cmod fp16 hi/lo, B = Wout fp16, 2-pass, scatter rows.
#define ROWB 80
#define TILEB (128*ROWB)             // 10240
#define NCHUNK 32                    // K=1024 / 32

template<int MODE>
__global__ void __launch_bounds__(256, 2) gemm_tc(
    const float* __restrict__ bias0, const float* __restrict__ bias1, float* __restrict__ out)
{
    constexpr int NT = (MODE == 0) ? 4 : 3;
    constexpr int STAGE = NT * TILEB;
    extern __shared__ char smem[];
    uint32_t sb = smem_u32(smem);
    const int t = threadIdx.x;
    const int wid = t >> 5;
    const int lane = t & 31;
    const int g  = lane >> 2;
    const int tg = lane & 3;
    const int wm = wid >> 1;
    const int wn = wid & 1;
    const int m0 = blockIdx.y * 128;
    const int n0 = blockIdx.x * 128;

    const char *A0, *A1, *B0, *B1 = nullptr;
    if (MODE == 0) { A0 = (const char*)g_xbh; A1 = (const char*)g_xbl;
                     B0 = (const char*)g_wbh; B1 = (const char*)g_wbl; }
    else if (MODE == 1) { A0 = (const char*)g_xfh; A1 = (const char*)g_xfl;
                          B0 = (const char*)g_wv; }
    else { A0 = (const char*)g_cmh; A1 = (const char*)g_cml;
           B0 = (const char*)g_wo; }

    const uint32_t aoff = (uint32_t)(lane & 15) * ROWB + ((lane >> 4) & 1) * 16;
    const uint32_t boff = (uint32_t)((lane & 7) + ((lane >> 4) & 1) * 8) * ROWB
                        + ((lane >> 3) & 1) * 16;

    float c[2][8][4];
    #pragma unroll
    for (int i = 0; i < 2; i++)
        #pragma unroll
        for (int j = 0; j < 8; j++)
            #pragma unroll
            for (int q = 0; q < 4; q++) c[i][j][q] = 0.f;

    // chunk loader: 64B per row (32 els x 2B), 2 iterations x 256 threads
    auto load_chunk = [&](uint32_t stage, int kc) {
        int kb = kc * 64;
        #pragma unroll
        for (int r = 0; r < 2; r++) {
            int j   = t + r * 256;
            int row = j >> 2;
            int cb  = j & 3;
            uint32_t d = (uint32_t)row * ROWB + cb * 16;
            int off = kb + cb * 16;
            CP_ASYNC16(stage + 0*TILEB + d, A0 + (size_t)(m0 + row) * 2048 + off);
            CP_ASYNC16(stage + 1*TILEB + d, A1 + (size_t)(m0 + row) * 2048 + off);
            CP_ASYNC16(stage + 2*TILEB + d, B0 + (size_t)(n0 + row) * 2048 + off);
            if (NT == 4)
                CP_ASYNC16(stage + 3*TILEB + d, B1 + (size_t)(n0 + row) * 2048 + off);
        }
    };

    load_chunk(sb, 0);
    CP_COMMIT();

    for (int kc = 0; kc < NCHUNK; kc++) {
        int buf = kc & 1;
        if (kc + 1 < NCHUNK) {
            load_chunk(sb + (buf ^ 1) * STAGE, kc + 1);
            CP_COMMIT();
            asm volatile("cp.async.wait_group 1;" ::: "memory");
        } else {
            asm volatile("cp.async.wait_group 0;" ::: "memory");
        }
        __syncthreads();

        uint32_t Ah = sb + buf * STAGE + 0*TILEB;
        uint32_t Al = sb + buf * STAGE + 1*TILEB;
        uint32_t Bh = sb + buf * STAGE + 2*TILEB;
        uint32_t Bl = sb + buf * STAGE + 3*TILEB;

        #pragma unroll
        for (int ks = 0; ks < 2; ks++) {
            uint32_t kcol = ks * 32;
            uint32_t ah[2][4], al[2][4];
            #pragma unroll
            for (int i = 0; i < 2; i++) {
                uint32_t rbase = (uint32_t)(wm * 32 + i * 16) * ROWB + kcol;
                ldsm_x4(ah[i], Ah + rbase + aoff);
                ldsm_x4(al[i], Al + rbase + aoff);
            }
            #pragma unroll
            for (int jj = 0; jj < 4; jj++) {
                uint32_t nbase = (uint32_t)(wn * 64 + jj * 16) * ROWB + kcol;
                if (MODE == 0) {
                    uint32_t bh[4], bl[4];
                    ldsm_x4(bh, Bh + nbase + boff);
                    ldsm_x4(bl, Bl + nbase + boff);
                    #pragma unroll
                    for (int i = 0; i < 2; i++) {
                        mma_bf(c[i][2*jj],   ah[i], bh);
                        mma_bf(c[i][2*jj],   ah[i], bl);
                        mma_bf(c[i][2*jj],   al[i], bh);
                        mma_bf(c[i][2*jj+1], ah[i], bh + 2);
                        mma_bf(c[i][2*jj+1], ah[i], bl + 2);
                        mma_bf(c[i][2*jj+1], al[i], bh + 2);
                    }
                } else {
                    uint32_t bq[4];
                    ldsm_x4(bq, Bh + nbase + boff);
                    #pragma unroll
                    for (int i = 0; i < 2; i++) {
                        mma_f16(c[i][2*jj],   ah[i], bq);
                        mma_f16(c[i][2*jj],   al[i], bq);
                        mma_f16(c[i][2*jj+1], ah[i], bq + 2);
                        mma_f16(c[i][2*jj+1], al[i], bq + 2);
                    }
                }
            }
        }
        __syncthreads();
    }

    // epilogue
    #pragma unroll
    for (int i = 0; i < 2; i++) {
        #pragma unroll
        for (int j = 0; j < 8; j++) {
            #pragma unroll
            for (int half = 0; half < 2; half++) {
                int m = m0 + wm * 32 + i * 16 + g + half * 8;
                int n = n0 + wn * 64 + j * 8 + 2 * tg;
                float v0 = c[i][j][half*2 + 0];
                float v1 = c[i][j][half*2 + 1];
                if (MODE == 0) {
                    int b_ = m >> 11, l = m & (LSEQ - 1);
                    int nloc = n & 1023;
                    int h = nloc >> 6, dh = nloc & 63;
                    const float* bias = (n < DMODEL) ? (bias0 + n) : (bias1 + n - DMODEL);
                    float* dst = ((n < DMODEL) ? g_Q : g_K)
                               + (((size_t)(b_ * NHEAD + h)) * LSEQ + l) * DHEAD + dh;
                    *(float2*)dst = make_float2(v0 + bias[0], v1 + bias[1]);
                } else if (MODE == 1) {
                    int b_ = m >> 11, l = m & (LSEQ - 1);
                    int h = n >> 6, dh = n & 63;
                    const float* bias = bias1 + DMODEL + n;   // bkv[1024 + n]
                    float* dst = g_V + (((size_t)(b_ * NHEAD + h)) * LSEQ + l) * DHEAD + dh;
                    *(float2*)dst = make_float2(v0 + bias[0], v1 + bias[1]);
                } else {
                    int b_ = m / MODROWS;
                    int i_ = m - b_ * MODROWS;
                    int l  = g_rowlist[b_ * MODROWS + i_];
                    *(float2*)(out + ((size_t)(b_ * LSEQ + l)) * DMODEL + n) =
                        make_float2(v0 + bias0[n], v1 + bias0[n + 1]);
                }
            }
        }
    }
}

// ================= M scores (fp32) =================
__global__ void score_m_kernel(const int* __restrict__ idxs)
{
    int warp = (blockIdx.x * blockDim.x + threadIdx.x) >> 5;
    int lane = threadIdx.x & 31;
    if (warp >= BHL) return;
    int l  = warp % LSEQ;
    int bh = warp / LSEQ;
    const float* qr = g_Q + (size_t)warp * DHEAD;
    float q0 = qr[lane], q1 = qr[lane + 32];
    float mx = -1e30f, sm = 0.f;
    #pragma unroll 4
    for (int u = 0; u < UTOP; u++) {
        int ki = idxs[l*UTOP + u];
        const float* kr = g_K + ((size_t)bh*LSEQ + ki)*DHEAD;
        float s = q0*kr[lane] + q1*kr[lane + 32];
        #pragma unroll
        for (int o = 16; o; o >>= 1) s += __shfl_xor_sync(0xffffffffu, s, o);
        mx = fmaxf(mx, s);
        sm += s;
    }
    if (lane == 0) g_M[warp] = mx - sm * (1.0f / UTOP);
}

// ================= top-U (shuffle-based) =================
__global__ void topk_kernel()
{
    int bh = blockIdx.x;
    __shared__ float vals[LSEQ];
    __shared__ float wv[8];
    __shared__ int   wi[8];
    int t = threadIdx.x, lane = t & 31, wid = t >> 5;
    for (int i = t; i < LSEQ; i += 256) vals[i] = g_M[(size_t)bh*LSEQ + i];
    __syncthreads();
    for (int it = 0; it < UTOP; it++) {
        float v = -2e30f; int bi = 0;
        int base = t * 8;
        #pragma unroll
        for (int j = 0; j < 8; j++) {
            float x = vals[base + j];
            if (x > v) { v = x; bi = base + j; }
        }
        #pragma unroll
        for (int o = 16; o; o >>= 1) {
            float ov = __shfl_xor_sync(0xffffffffu, v, o);
            int   oi = __shfl_xor_sync(0xffffffffu, bi, o);
            if (ov > v) { v = ov; bi = oi; }
        }
        if (lane == 0) { wv[wid] = v; wi[wid] = bi; }
        __syncthreads();
        if (t < 32) {
            float v2 = (t < 8) ? wv[t] : -2e30f;
            int   i2 = (t < 8) ? wi[t] : 0;
            #pragma unroll
            for (int o = 4; o; o >>= 1) {
                float ov = __shfl_xor_sync(0xffffffffu, v2, o);
                int   oi = __shfl_xor_sync(0xffffffffu, i2, o);
                if (ov > v2) { v2 = ov; i2 = oi; }
            }
            if (t == 0) { g_top[bh*UTOP + it] = i2; vals[i2] = -1e30f; }
        }
        __syncthreads();
    }
}

// ================= V mean =================
__global__ void vmean_part()
{
    int p = blockIdx.x, bh = blockIdx.y, dh = threadIdx.x;
    float s = 0.f;
    const float* base = g_V + ((size_t)bh*LSEQ + p*KS_KEYS)*DHEAD + dh;
    #pragma unroll 4
    for (int j = 0; j < KS_KEYS; j++) s += base[(size_t)j*DHEAD];
    g_vpart[((size_t)bh*KSPLIT + p)*DHEAD + dh] = s;
}
__global__ void vmean_fin()
{
    int bh = blockIdx.x, dh = threadIdx.x;
    float s = 0.f;
    #pragma unroll
    for (int p = 0; p < KSPLIT; p++) s += g_vpart[((size_t)bh*KSPLIT + p)*DHEAD + dh];
    g_vmean[bh*DHEAD + dh] = s * (1.0f / LSEQ);
}

// ================= flash-split attention =================
__global__ void attn_flash()
{
    extern __shared__ float sm[];
    float* Qt   = sm;                        // [40][64]
    float* P    = sm + UTOP*DHEAD;           // [40][256]
    float* mrow = P + UTOP*KS_KEYS;          // [40]
    float* srow = mrow + UTOP;               // [40]
    int ks = blockIdx.x, bh = blockIdx.y;
    int t = threadIdx.x, lane = t & 31, wid = t >> 5;

    for (int i = t; i < UTOP*DHEAD; i += 256) {
        int u = i >> 6, d = i & 63;
        Qt[i] = g_Q[((size_t)bh*LSEQ + g_top[bh*UTOP + u])*DHEAD + d];
    }
    __syncthreads();

    int k = ks * KS_KEYS + t;
    const float4* Kr = (const float4*)(g_K + ((size_t)bh*LSEQ + k)*DHEAD);
    float S[UTOP];
    #pragma unroll
    for (int u = 0; u < UTOP; u++) S[u] = 0.f;
    #pragma unroll
    for (int c = 0; c < 16; c++) {
        float4 kv = Kr[c];
        #pragma unroll
        for (int u = 0; u < UTOP; u++) {
            float4 qv = *(const float4*)(Qt + u*DHEAD + c*4);
            S[u] += kv.x*qv.x + kv.y*qv.y + kv.z*qv.z + kv.w*qv.w;
        }
    }
    #pragma unroll
    for (int u = 0; u < UTOP; u++) P[u*KS_KEYS + t] = S[u] * 0.125f;
    __syncthreads();

    for (int i = 0; i < 5; i++) {
        int u = wid + i*8;
        float* row = P + u*KS_KEYS;
        float m = -1e30f;
        #pragma unroll
        for (int j = 0; j < 8; j++) m = fmaxf(m, row[lane + 32*j]);
        #pragma unroll
        for (int o = 16; o; o >>= 1) m = fmaxf(m, __shfl_xor_sync(0xffffffffu, m, o));
        float s = 0.f;
        #pragma unroll
        for (int j = 0; j < 8; j++) {
            float e = __expf(row[lane + 32*j] - m);
            row[lane + 32*j] = e;
            s += e;
        }
        #pragma unroll
        for (int o = 16; o; o >>= 1) s += __shfl_xor_sync(0xffffffffu, s, o);
        if (lane == 0) { mrow[u] = m; srow[u] = s; }
    }
    __syncthreads();

    int d = t & 63, ug = t >> 6;
    float acc[10];
    #pragma unroll
    for (int i = 0; i < 10; i++) acc[i] = 0.f;
    const float* Vb = g_V + ((size_t)bh*LSEQ + ks*KS_KEYS)*DHEAD + d;
    for (int kc = 0; kc < KS_KEYS/4; kc++) {
        float v0 = Vb[(size_t)(kc*4+0)*DHEAD];
        float v1 = Vb[(size_t)(kc*4+1)*DHEAD];
        float v2 = Vb[(size_t)(kc*4+2)*DHEAD];
        float v3 = Vb[(size_t)(kc*4+3)*DHEAD];
        #pragma unroll
        for (int i = 0; i < 10; i++) {
            int u = ug*10 + i;
            float4 p4 = *(const float4*)(P + u*KS_KEYS + kc*4);
            acc[i] += p4.x*v0 + p4.y*v1 + p4.z*v2 + p4.w*v3;
        }
    }
    #pragma unroll
    for (int i = 0; i < 10; i++) {
        int u = ug*10 + i;
        g_pa[(((size_t)(bh*UTOP + u))*KSPLIT + ks)*DHEAD + d] = acc[i];
    }
    if (t < UTOP) {
        g_pm[(bh*UTOP + t)*KSPLIT + ks] = mrow[t];
        g_ps[(bh*UTOP + t)*KSPLIT + ks] = srow[t];
    }
}

__global__ void attn_combine()
{
    int bhu = blockIdx.x;
    int d = threadIdx.x;
    float m = -1e30f;
    #pragma unroll
    for (int j = 0; j < KSPLIT; j++) m = fmaxf(m, g_pm[bhu*KSPLIT + j]);
    float s = 0.f, a = 0.f;
    #pragma unroll
    for (int j = 0; j < KSPLIT; j++) {
        float w = __expf(g_pm[bhu*KSPLIT + j] - m);
        s += w * g_ps[bhu*KSPLIT + j];
        a += w * g_pa[((size_t)bhu*KSPLIT + j)*DHEAD + d];
    }
    g_ctx[(size_t)bhu*DHEAD + d] = a / s;
}

// ================= output-projection compaction =================
__global__ void sel_clear()
{
    int i = blockIdx.x * blockDim.x + threadIdx.x;
    g_selu[i] = 0;
    if (i < BATCH*LSEQ) g_flags[i] = 0;
}
__global__ void sel_mark()
{
    int bh = blockIdx.x, u = threadIdx.x;
    int l = g_top[bh*UTOP + u];
    g_selu[bh*LSEQ + l] = (unsigned char)(u + 1);
    int b_ = bh / NHEAD;
    g_flags[b_*LSEQ + l] = 1;
}
__global__ void compact_kernel()
{
    int b = blockIdx.x, t = threadIdx.x;
    __shared__ int cnts[256];
    __shared__ int l0s;
    int mine[8];
    int cnt = 0;
    #pragma unroll
    for (int j = 0; j < 8; j++) {
        mine[j] = g_flags[b*LSEQ + t*8 + j];
        cnt += mine[j];
    }
    cnts[t] = cnt;
    __syncthreads();
    for (int off = 1; off < 256; off <<= 1) {
        int v = (t >= off) ? cnts[t - off] : 0;
        __syncthreads();
        cnts[t] += v;
        __syncthreads();
    }
    int pos = cnts[t] - cnt;
    int total = cnts[255];
    #pragma unroll
    for (int j = 0; j < 8; j++)
        if (mine[j]) g_rowlist[b*MODROWS + pos++] = t*8 + j;
    __syncthreads();
    if (t == 0) l0s = g_rowlist[b*MODROWS];
    __syncthreads();
    for (int i = total + t; i < MODROWS; i += 256) g_rowlist[b*MODROWS + i] = l0s;
}
__global__ void build_cmod()
{
    int idx = blockIdx.x * blockDim.x + threadIdx.x;
    int d = idx & 1023;
    int r = (idx >> 10) % MODROWS;
    int b = idx / (MODROWS * 1024);
    int l = g_rowlist[b*MODROWS + r];
    int h = d >> 6;
    int bh = b * NHEAD + h;
    unsigned char u = g_selu[bh*LSEQ + l];
    float v = u ? g_ctx[((size_t)bh*UTOP + (u-1))*DHEAD + (d & 63)]
                : g_vmean[bh*DHEAD + (d & 63)];
    __half hi = __float2half(v);
    g_cmh[idx] = hi;
    g_cml[idx] = __float2half(v - __half2float(hi));
}
__global__ void base_out_kernel(const float* __restrict__ Wout, const float* __restrict__ bout)
{
    int gid = blockIdx.x * 8 + (threadIdx.x >> 5);
    int lane = threadIdx.x & 31;
    int b = gid >> 10, n = gid & 1023;
    const float* w = Wout + (size_t)n * DMODEL;
    const float* cb = g_vmean + b * DMODEL;
    float s = 0.f;
    #pragma unroll 8
    for (int k = lane; k < DMODEL; k += 32) s += cb[k] * w[k];
    #pragma unroll
    for (int o = 16; o; o >>= 1) s += __shfl_xor_sync(0xffffffffu, s, o);
    if (lane == 0) g_baseout[b*DMODEL + n] = s + bout[n];
}
__global__ void broadcast_base(float* __restrict__ out)
{
    int idx = blockIdx.x * blockDim.x + threadIdx.x;
    int e = idx * 4;
    int b = e >> 21;
    float4 v = *(const float4*)(g_baseout + b*DMODEL + (e & 1023));
    *(float4*)(out + e) = v;
}

// -----------------------------------------------------------------------------
extern "C" void kernel_launch(void* const* d_in, const int* in_sizes, int n_in,
                              void* d_out, int out_size)
{
    const float* x    = (const float*)d_in[0];
    const float* Wq   = (const float*)d_in[1];
    const float* bq   = (const float*)d_in[2];
    const float* Wkv  = (const float*)d_in[3];
    const float* bkv  = (const float*)d_in[4];
    const float* Wout = (const float*)d_in[5];
    const float* bout = (const float*)d_in[6];
    const int*   idxs = (const int*)d_in[7];
    float* out = (float*)d_out;

    cudaFuncSetAttribute(gemm_tc<0>, cudaFuncAttributeMaxDynamicSharedMemorySize, 2*4*TILEB);
    cudaFuncSetAttribute(gemm_tc<1>, cudaFuncAttributeMaxDynamicSharedMemorySize, 2*3*TILEB);
    cudaFuncSetAttribute(gemm_tc<2>, cudaFuncAttributeMaxDynamicSharedMemorySize, 2*3*TILEB);
    int attn_smem = (UTOP*DHEAD + UTOP*KS_KEYS + 2*UTOP) * sizeof(float);
    cudaFuncSetAttribute(attn_flash, cudaFuncAttributeMaxDynamicSharedMemorySize, attn_smem);

    // conversions
    splitX<<<MROWS*DMODEL/256, 256>>>(x);
    splitWb<<<2*DD/256, 256>>>(Wq, Wkv);
    convH<<<2*DD/256, 256>>>(Wkv, Wout);

    // QK projection (bf16 3-pass) and V projection (fp16 2-pass)
    gemm_tc<0><<<dim3(2*DMODEL/128, MROWS/128), 256, 2*4*TILEB>>>(bq, bkv, nullptr);
    gemm_tc<1><<<dim3(DMODEL/128, MROWS/128), 256, 2*3*TILEB>>>(nullptr, bkv, nullptr);
    // sparsity measure + selection
    score_m_kernel<<<BHL/8, 256>>>(idxs);
    topk_kernel<<<BATCH*NHEAD, 256>>>();
    // selection maps + compaction
    sel_clear<<<256, 256>>>();
    sel_mark<<<BATCH*NHEAD, UTOP>>>();
    compact_kernel<<<BATCH, 256>>>();
    // V mean
    vmean_part<<<dim3(KSPLIT, BATCH*NHEAD), 64>>>();
    vmean_fin<<<BATCH*NHEAD, 64>>>();
    // flash-split attention over selected queries
    attn_flash<<<dim3(KSPLIT, BATCH*NHEAD), 256, attn_smem>>>();
    attn_combine<<<BATCH*NHEAD*UTOP, 64>>>();
    // base output rows (exact fp32) + broadcast
    base_out_kernel<<<BATCH*DMODEL/8, 256>>>(Wout, bout);
    broadcast_base<<<MROWS*DMODEL/1024, 256>>>(out);
    // modified context rows -> fp16 split -> scatter GEMM (fp16 2-pass)
    build_cmod<<<BATCH*MODROWS*DMODEL/256, 256>>>();
    gemm_tc<2><<<dim3(DMODEL/128, BATCH*MODROWS/128), 256, 2*3*TILEB>>>(bout, nullptr, out);
}

// round 8
// speedup vs baseline: 3.4061x; 1.1047x over previous
#include <cuda_runtime.h>
#include <cuda_bf16.h>
#include <cuda_fp16.h>
#include <cstdint>
#include <math.h>

#define BATCH 2
#define LSEQ 2048
#define DMODEL 1024
#define NHEAD 16
#define DHEAD 64
#define UTOP 40
#define MROWS (BATCH*LSEQ)          // 4096
#define BHL (BATCH*NHEAD*LSEQ)      // 65536
#define KSPLIT 8
#define KS_KEYS (LSEQ/KSPLIT)       // 256
#define MODROWS 640
#define DD (DMODEL*DMODEL)

// ---------------- scratch ----------------
__device__ float g_Q[BATCH*NHEAD*LSEQ*DHEAD];
__device__ float g_K[BATCH*NHEAD*LSEQ*DHEAD];
__device__ float g_V[BATCH*NHEAD*LSEQ*DHEAD];
__device__ float g_M[BHL];
__device__ int   g_top[BATCH*NHEAD*UTOP];
__device__ float g_ctx[BATCH*NHEAD*UTOP*DHEAD];
__device__ float g_vpart[BATCH*NHEAD*KSPLIT*DHEAD];
__device__ float g_vmean[BATCH*NHEAD*DHEAD];
__device__ __nv_bfloat16 g_xbh[MROWS*DMODEL], g_xbl[MROWS*DMODEL];
__device__ __half        g_xfh[MROWS*DMODEL], g_xfl[MROWS*DMODEL];
__device__ __nv_bfloat16 g_wbh[2*DD], g_wbl[2*DD];   // [Wq ; Wkv_K] bf16 hi/lo
__device__ __half        g_wv[DD];                   // Wkv_V fp16
__device__ __half        g_wo[DD];                   // Wout fp16
__device__ __half        g_cmh[BATCH*MODROWS*DMODEL], g_cml[BATCH*MODROWS*DMODEL];
__device__ float g_pm[BATCH*NHEAD*UTOP*KSPLIT];
__device__ float g_ps[BATCH*NHEAD*UTOP*KSPLIT];
__device__ float g_pa[BATCH*NHEAD*UTOP*KSPLIT*DHEAD];
__device__ unsigned char g_selu[BATCH*NHEAD*LSEQ];
__device__ int   g_flags[BATCH*LSEQ];
__device__ int   g_rowlist[BATCH*MODROWS];
__device__ float g_baseout[BATCH*DMODEL];

// ================= helpers =================
#define CP_ASYNC16(dst, src) \
    asm volatile("cp.async.cg.shared.global [%0], [%1], 16;" :: "r"(dst), "l"(src))
#define CP_COMMIT() asm volatile("cp.async.commit_group;" ::: "memory")

__device__ __forceinline__ uint32_t smem_u32(const void* p) {
    uint32_t a;
    asm("{ .reg .u64 t; cvta.to.shared.u64 t, %1; cvt.u32.u64 %0, t; }" : "=r"(a) : "l"(p));
    return a;
}
__device__ __forceinline__ void mma_bf(float* c, const uint32_t* a, const uint32_t* b) {
    asm volatile("mma.sync.aligned.m16n8k16.row.col.f32.bf16.bf16.f32 "
        "{%0,%1,%2,%3}, {%4,%5,%6,%7}, {%8,%9}, {%0,%1,%2,%3};"
        : "+f"(c[0]), "+f"(c[1]), "+f"(c[2]), "+f"(c[3])
        : "r"(a[0]), "r"(a[1]), "r"(a[2]), "r"(a[3]), "r"(b[0]), "r"(b[1]));
}
__device__ __forceinline__ void mma_f16(float* c, const uint32_t* a, const uint32_t* b) {
    asm volatile("mma.sync.aligned.m16n8k16.row.col.f32.f16.f16.f32 "
        "{%0,%1,%2,%3}, {%4,%5,%6,%7}, {%8,%9}, {%0,%1,%2,%3};"
        : "+f"(c[0]), "+f"(c[1]), "+f"(c[2]), "+f"(c[3])
        : "r"(a[0]), "r"(a[1]), "r"(a[2]), "r"(a[3]), "r"(b[0]), "r"(b[1]));
}
__device__ __forceinline__ void ldsm_x4(uint32_t* r, uint32_t addr) {
    asm volatile("ldmatrix.sync.aligned.m8n8.x4.shared.b16 {%0,%1,%2,%3}, [%4];"
        : "=r"(r[0]), "=r"(r[1]), "=r"(r[2]), "=r"(r[3]) : "r"(addr));
}
// 64B rows, 4x16B blocks, XOR swizzle by row&3
__device__ __forceinline__ uint32_t sw_addr(uint32_t tile, int row, int cb) {
    return tile + (uint32_t)row * 64 + (uint32_t)((cb ^ (row & 3)) << 4);
}

// ================= conversions =================
__global__ void splitX(const float* __restrict__ src)
{
    int i = blockIdx.x * blockDim.x + threadIdx.x;
    float v = src[i];
    __nv_bfloat16 bh = __float2bfloat16(v);
    g_xbh[i] = bh;
    g_xbl[i] = __float2bfloat16(v - __bfloat162float(bh));
    __half fh = __float2half(v);
    g_xfh[i] = fh;
    g_xfl[i] = __float2half(v - __half2float(fh));
}
__global__ void splitWb(const float* __restrict__ Wq, const float* __restrict__ Wkv)
{
    int i = blockIdx.x * blockDim.x + threadIdx.x;
    float v = (i < DD) ? Wq[i] : Wkv[i - DD];
    __nv_bfloat16 h = __float2bfloat16(v);
    g_wbh[i] = h;
    g_wbl[i] = __float2bfloat16(v - __bfloat162float(h));
}
__global__ void convH(const float* __restrict__ Wkv, const float* __restrict__ Wout)
{
    int i = blockIdx.x * blockDim.x + threadIdx.x;
    if (i < DD) g_wv[i] = __float2half(Wkv[DD + i]);
    else        g_wo[i - DD] = __float2half(Wout[i - DD]);
}

// ================= tensor-core GEMM =================
// CTA tile 128x128, 8 warps 4x2, warp tile 32x64, K-chunk 32, 3-stage pipeline,
// XOR-swizzled 64B rows, ONE __syncthreads per chunk, 2 CTAs/SM.
// MODE 0: QK bf16 3-pass (N=2048), MODE 1: V fp16 2-pass, MODE 2: OUT fp16 2-pass.
#define TILEB 8192                   // 128 rows x 64B
#define NCHUNK 32
#define NSTAGE 3

template<int MODE>
__global__ void __launch_bounds__(256, 2) gemm_tc(
    const float* __restrict__ bias0, const float* __restrict__ bias1, float* __restrict__ out)
{
    constexpr int NT = (MODE == 0) ? 4 : 3;
    constexpr int STAGE = NT * TILEB;
    extern __shared__ char smem[];
    uint32_t sb = smem_u32(smem);
    const int t = threadIdx.x;
    const int wid = t >> 5;
    const int lane = t & 31;
    const int g  = lane >> 2;
    const int tg = lane & 3;
    const int wm = wid >> 1;
    const int wn = wid & 1;
    const int m0 = blockIdx.y * 128;
    const int n0 = blockIdx.x * 128;

    const char *A0, *A1, *B0, *B1 = nullptr;
    if (MODE == 0) { A0 = (const char*)g_xbh; A1 = (const char*)g_xbl;
                     B0 = (const char*)g_wbh; B1 = (const char*)g_wbl; }
    else if (MODE == 1) { A0 = (const char*)g_xfh; A1 = (const char*)g_xfl;
                          B0 = (const char*)g_wv; }
    else { A0 = (const char*)g_cmh; A1 = (const char*)g_cml;
           B0 = (const char*)g_wo; }

    const int arow = lane & 15;
    const int acb  = (lane >> 4) & 1;
    const int brow = (lane & 7) + ((lane >> 4) & 1) * 8;
    const int bcb  = (lane >> 3) & 1;

    float c[2][8][4];
    #pragma unroll
    for (int i = 0; i < 2; i++)
        #pragma unroll
        for (int j = 0; j < 8; j++)
            #pragma unroll
            for (int q = 0; q < 4; q++) c[i][j][q] = 0.f;

    auto load_chunk = [&](uint32_t stage, int kc) {
        int kb = kc * 64;
        #pragma unroll
        for (int r = 0; r < 2; r++) {
            int j   = t + r * 256;
            int row = j >> 2;
            int cb  = j & 3;
            uint32_t d = (uint32_t)row * 64 + (uint32_t)((cb ^ (row & 3)) << 4);
            int off = kb + cb * 16;
            CP_ASYNC16(stage + 0*TILEB + d, A0 + (size_t)(m0 + row) * 2048 + off);
            CP_ASYNC16(stage + 1*TILEB + d, A1 + (size_t)(m0 + row) * 2048 + off);
            CP_ASYNC16(stage + 2*TILEB + d, B0 + (size_t)(n0 + row) * 2048 + off);
            if (NT == 4)
                CP_ASYNC16(stage + 3*TILEB + d, B1 + (size_t)(n0 + row) * 2048 + off);
        }
    };

    load_chunk(sb, 0);               CP_COMMIT();
    load_chunk(sb + STAGE, 1);       CP_COMMIT();

    int stg = 0;
    for (int kc = 0; kc < NCHUNK; kc++) {
        if (kc < NCHUNK - 1) asm volatile("cp.async.wait_group 1;" ::: "memory");
        else                 asm volatile("cp.async.wait_group 0;" ::: "memory");
        __syncthreads();

        uint32_t Ah = sb + stg * STAGE + 0*TILEB;
        uint32_t Al = sb + stg * STAGE + 1*TILEB;
        uint32_t Bh = sb + stg * STAGE + 2*TILEB;
        uint32_t Bl = sb + stg * STAGE + 3*TILEB;

        #pragma unroll
        for (int ks = 0; ks < 2; ks++) {
            uint32_t ah[2][4], al[2][4];
            #pragma unroll
            for (int i = 0; i < 2; i++) {
                int row = wm * 32 + i * 16 + arow;
                int cb  = ks * 2 + acb;
                ldsm_x4(ah[i], sw_addr(Ah, row, cb));
                ldsm_x4(al[i], sw_addr(Al, row, cb));
            }
            #pragma unroll
            for (int jj = 0; jj < 4; jj++) {
                int row = wn * 64 + jj * 16 + brow;
                int cb  = ks * 2 + bcb;
                if (MODE == 0) {
                    uint32_t bh[4], bl[4];
                    ldsm_x4(bh, sw_addr(Bh, row, cb));
                    ldsm_x4(bl, sw_addr(Bl, row, cb));
                    #pragma unroll
                    for (int i = 0; i < 2; i++) {
                        mma_bf(c[i][2*jj],   ah[i], bh);
                        mma_bf(c[i][2*jj],   ah[i], bl);
                        mma_bf(c[i][2*jj],   al[i], bh);
                        mma_bf(c[i][2*jj+1], ah[i], bh + 2);
                        mma_bf(c[i][2*jj+1], ah[i], bl + 2);
                        mma_bf(c[i][2*jj+1], al[i], bh + 2);
                    }
                } else {
                    uint32_t bq[4];
                    ldsm_x4(bq, sw_addr(Bh, row, cb));
                    #pragma unroll
                    for (int i = 0; i < 2; i++) {
                        mma_f16(c[i][2*jj],   ah[i], bq);
                        mma_f16(c[i][2*jj],   al[i], bq);
                        mma_f16(c[i][2*jj+1], ah[i], bq + 2);
                        mma_f16(c[i][2*jj+1], al[i], bq + 2);
                    }
                }
            }
        }
        if (kc + 2 < NCHUNK) {
            int nstg = stg + 2; if (nstg >= NSTAGE) nstg -= NSTAGE;
            load_chunk(sb + nstg * STAGE, kc + 2);
            CP_COMMIT();
        }
        stg = (stg + 1 == NSTAGE) ? 0 : stg + 1;
    }

    // epilogue
    #pragma unroll
    for (int i = 0; i < 2; i++) {
        #pragma unroll
        for (int j = 0; j < 8; j++) {
            #pragma unroll
            for (int half = 0; half < 2; half++) {
                int m = m0 + wm * 32 + i * 16 + g + half * 8;
                int n = n0 + wn * 64 + j * 8 + 2 * tg;
                float v0 = c[i][j][half*2 + 0];
                float v1 = c[i][j][half*2 + 1];
                if (MODE == 0) {
                    int b_ = m >> 11, l = m & (LSEQ - 1);
                    int nloc = n & 1023;
                    int h = nloc >> 6, dh = nloc & 63;
                    const float* bias = (n < DMODEL) ? (bias0 + n) : (bias1 + n - DMODEL);
                    float* dst = ((n < DMODEL) ? g_Q : g_K)
                               + (((size_t)(b_ * NHEAD + h)) * LSEQ + l) * DHEAD + dh;
                    *(float2*)dst = make_float2(v0 + bias[0], v1 + bias[1]);
                } else if (MODE == 1) {
                    int b_ = m >> 11, l = m & (LSEQ - 1);
                    int h = n >> 6, dh = n & 63;
                    const float* bias = bias1 + DMODEL + n;
                    float* dst = g_V + (((size_t)(b_ * NHEAD + h)) * LSEQ + l) * DHEAD + dh;
                    *(float2*)dst = make_float2(v0 + bias[0], v1 + bias[1]);
                } else {
                    int b_ = m / MODROWS;
                    int i_ = m - b_ * MODROWS;
                    int l  = g_rowlist[b_ * MODROWS + i_];
                    *(float2*)(out + ((size_t)(b_ * LSEQ + l)) * DMODEL + n) =
                        make_float2(v0 + bias0[n], v1 + bias0[n + 1]);
                }
            }
        }
    }
}

// ================= M scores (fp32 — selection path is precision-frozen) =======
__global__ void score_m_kernel(const int* __restrict__ idxs)
{
    int warp = (blockIdx.x * blockDim.x + threadIdx.x) >> 5;
    int lane = threadIdx.x & 31;
    if (warp >= BHL) return;
    int l  = warp % LSEQ;
    int bh = warp / LSEQ;
    const float* qr = g_Q + (size_t)warp * DHEAD;
    float q0 = qr[lane], q1 = qr[lane + 32];
    float mx = -1e30f, sm = 0.f;
    #pragma unroll 4
    for (int u = 0; u < UTOP; u++) {
        int ki = idxs[l*UTOP + u];
        const float* kr = g_K + ((size_t)bh*LSEQ + ki)*DHEAD;
        float s = q0*kr[lane] + q1*kr[lane + 32];
        #pragma unroll
        for (int o = 16; o; o >>= 1) s += __shfl_xor_sync(0xffffffffu, s, o);
        mx = fmaxf(mx, s);
        sm += s;
    }
    if (lane == 0) g_M[warp] = mx - sm * (1.0f / UTOP);
}

// ================= top-U =================
__global__ void topk_kernel()
{
    int bh = blockIdx.x;
    __shared__ float vals[LSEQ];
    __shared__ float wv[8];
    __shared__ int   wi[8];
    int t = threadIdx.x, lane = t & 31, wid = t >> 5;
    for (int i = t; i < LSEQ; i += 256) vals[i] = g_M[(size_t)bh*LSEQ + i];
    __syncthreads();
    for (int it = 0; it < UTOP; it++) {
        float v = -2e30f; int bi = 0;
        int base = t * 8;
        #pragma unroll
        for (int j = 0; j < 8; j++) {
            float x = vals[base + j];
            if (x > v) { v = x; bi = base + j; }
        }
        #pragma unroll
        for (int o = 16; o; o >>= 1) {
            float ov = __shfl_xor_sync(0xffffffffu, v, o);
            int   oi = __shfl_xor_sync(0xffffffffu, bi, o);
            if (ov > v) { v = ov; bi = oi; }
        }
        if (lane == 0) { wv[wid] = v; wi[wid] = bi; }
        __syncthreads();
        if (t < 32) {
            float v2 = (t < 8) ? wv[t] : -2e30f;
            int   i2 = (t < 8) ? wi[t] : 0;
            #pragma unroll
            for (int o = 4; o; o >>= 1) {
                float ov = __shfl_xor_sync(0xffffffffu, v2, o);
                int   oi = __shfl_xor_sync(0xffffffffu, i2, o);
                if (ov > v2) { v2 = ov; i2 = oi; }
            }
            if (t == 0) { g_top[bh*UTOP + it] = i2; vals[i2] = -1e30f; }
        }
        __syncthreads();
    }
}

// ================= V mean finish =================
__global__ void vmean_fin()
{
    int bh = blockIdx.x, dh = threadIdx.x;
    float s = 0.f;
    #pragma unroll
    for (int p = 0; p < KSPLIT; p++) s += g_vpart[((size_t)bh*KSPLIT + p)*DHEAD + dh];
    g_vmean[bh*DHEAD + dh] = s * (1.0f / LSEQ);
}

// ================= flash-split attention (+ V-mean partials) =================
__global__ void attn_flash()
{
    extern __shared__ float sm[];
    float* Qt   = sm;                        // [40][64]
    float* P    = sm + UTOP*DHEAD;           // [40][256]
    float* mrow = P + UTOP*KS_KEYS;          // [40]
    float* srow = mrow + UTOP;               // [40]
    int ks = blockIdx.x, bh = blockIdx.y;
    int t = threadIdx.x, lane = t & 31, wid = t >> 5;

    for (int i = t; i < UTOP*DHEAD; i += 256) {
        int u = i >> 6, d = i & 63;
        Qt[i] = g_Q[((size_t)bh*LSEQ + g_top[bh*UTOP + u])*DHEAD + d];
    }
    __syncthreads();

    int k = ks * KS_KEYS + t;
    const float4* Kr = (const float4*)(g_K + ((size_t)bh*LSEQ + k)*DHEAD);
    float S[UTOP];
    #pragma unroll
    for (int u = 0; u < UTOP; u++) S[u] = 0.f;
    #pragma unroll
    for (int c = 0; c < 16; c++) {
        float4 kv = Kr[c];
        #pragma unroll
        for (int u = 0; u < UTOP; u++) {
            float4 qv = *(const float4*)(Qt + u*DHEAD + c*4);
            S[u] += kv.x*qv.x + kv.y*qv.y + kv.z*qv.z + kv.w*qv.w;
        }
    }
    #pragma unroll
    for (int u = 0; u < UTOP; u++) P[u*KS_KEYS + t] = S[u] * 0.125f;
    __syncthreads();

    for (int i = 0; i < 5; i++) {
        int u = wid + i*8;
        float* row = P + u*KS_KEYS;
        float m = -1e30f;
        #pragma unroll
        for (int j = 0; j < 8; j++) m = fmaxf(m, row[lane + 32*j]);
        #pragma unroll
        for (int o = 16; o; o >>= 1) m = fmaxf(m, __shfl_xor_sync(0xffffffffu, m, o));
        float s = 0.f;
        #pragma unroll
        for (int j = 0; j < 8; j++) {
            float e = __expf(row[lane + 32*j] - m);
            row[lane + 32*j] = e;
            s += e;
        }
        #pragma unroll
        for (int o = 16; o; o >>= 1) s += __shfl_xor_sync(0xffffffffu, s, o);
        if (lane == 0) { mrow[u] = m; srow[u] = s; }
    }
    __syncthreads();

    int d = t & 63, ug = t >> 6;
    float acc[10];
    #pragma unroll
    for (int i = 0; i < 10; i++) acc[i] = 0.f;
    float msum = 0.f;
    const float* Vb = g_V + ((size_t)bh*LSEQ + ks*KS_KEYS)*DHEAD + d;
    for (int kc = 0; kc < KS_KEYS/4; kc++) {
        float v0 = Vb[(size_t)(kc*4+0)*DHEAD];
        float v1 = Vb[(size_t)(kc*4+1)*DHEAD];
        float v2 = Vb[(size_t)(kc*4+2)*DHEAD];
        float v3 = Vb[(size_t)(kc*4+3)*DHEAD];
        msum += v0 + v1 + v2 + v3;
        #pragma unroll
        for (int i = 0; i < 10; i++) {
            int u = ug*10 + i;
            float4 p4 = *(const float4*)(P + u*KS_KEYS + kc*4);
            acc[i] += p4.x*v0 + p4.y*v1 + p4.z*v2 + p4.w*v3;
        }
    }
    if (ug == 0)
        g_vpart[((size_t)bh*KSPLIT + ks)*DHEAD + d] = msum;
    #pragma unroll
    for (int i = 0; i < 10; i++) {
        int u = ug*10 + i;
        g_pa[(((size_t)(bh*UTOP + u))*KSPLIT + ks)*DHEAD + d] = acc[i];
    }
    if (t < UTOP) {
        g_pm[(bh*UTOP + t)*KSPLIT + ks] = mrow[t];
        g_ps[(bh*UTOP + t)*KSPLIT + ks] = srow[t];
    }
}

__global__ void attn_combine()
{
    int bhu = blockIdx.x;
    int d = threadIdx.x;
    float m = -1e30f;
    #pragma unroll
    for (int j = 0; j < KSPLIT; j++) m = fmaxf(m, g_pm[bhu*KSPLIT + j]);
    float s = 0.f, a = 0.f;
    #pragma unroll
    for (int j = 0; j < KSPLIT; j++) {
        float w = __expf(g_pm[bhu*KSPLIT + j] - m);
        s += w * g_ps[bhu*KSPLIT + j];
        a += w * g_pa[((size_t)bhu*KSPLIT + j)*DHEAD + d];
    }
    g_ctx[(size_t)bhu*DHEAD + d] = a / s;
}

// ================= output-projection compaction =================
__global__ void sel_clear()
{
    int i = blockIdx.x * blockDim.x + threadIdx.x;
    g_selu[i] = 0;
    if (i < BATCH*LSEQ) g_flags[i] = 0;
}
__global__ void sel_mark()
{
    int bh = blockIdx.x, u = threadIdx.x;
    int l = g_top[bh*UTOP + u];
    g_selu[bh*LSEQ + l] = (unsigned char)(u + 1);
    int b_ = bh / NHEAD;
    g_flags[b_*LSEQ + l] = 1;
}
__global__ void compact_kernel()
{
    int b = blockIdx.x, t = threadIdx.x;
    __shared__ int cnts[256];
    __shared__ int l0s;
    int mine[8];
    int cnt = 0;
    #pragma unroll
    for (int j = 0; j < 8; j++) {
        mine[j] = g_flags[b*LSEQ + t*8 + j];
        cnt += mine[j];
    }
    cnts[t] = cnt;
    __syncthreads();
    for (int off = 1; off < 256; off <<= 1) {
        int v = (t >= off) ? cnts[t - off] : 0;
        __syncthreads();
        cnts[t] += v;
        __syncthreads();
    }
    int pos = cnts[t] - cnt;
    int total = cnts[255];
    #pragma unroll
    for (int j = 0; j < 8; j++)
        if (mine[j]) g_rowlist[b*MODROWS + pos++] = t*8 + j;
    __syncthreads();
    if (t == 0) l0s = g_rowlist[b*MODROWS];
    __syncthreads();
    for (int i = total + t; i < MODROWS; i += 256) g_rowlist[b*MODROWS + i] = l0s;
}
__global__ void build_cmod()
{
    int idx = blockIdx.x * blockDim.x + threadIdx.x;
    int d = idx & 1023;
    int r = (idx >> 10) % MODROWS;
    int b = idx / (MODROWS * 1024);
    int l = g_rowlist[b*MODROWS + r];
    int h = d >> 6;
    int bh = b * NHEAD + h;
    unsigned char u = g_selu[bh*LSEQ + l];
    float v = u ? g_ctx[((size_t)bh*UTOP + (u-1))*DHEAD + (d & 63)]
                : g_vmean[bh*DHEAD + (d & 63)];
    __half hi = __float2half(v);
    g_cmh[idx] = hi;
    g_cml[idx] = __float2half(v - __half2float(hi));
}
__global__ void base_out_kernel(const float* __restrict__ Wout, const float* __restrict__ bout)
{
    int gid = blockIdx.x * 8 + (threadIdx.x >> 5);
    int lane = threadIdx.x & 31;
    int b = gid >> 10, n = gid & 1023;
    const float* w = Wout + (size_t)n * DMODEL;
    const float* cb = g_vmean + b * DMODEL;
    float s = 0.f;
    #pragma unroll 8
    for (int k = lane; k < DMODEL; k += 32) s += cb[k] * w[k];
    #pragma unroll
    for (int o = 16; o; o >>= 1) s += __shfl_xor_sync(0xffffffffu, s, o);
    if (lane == 0) g_baseout[b*DMODEL + n] = s + bout[n];
}
__global__ void broadcast_base(float* __restrict__ out)
{
    int idx = blockIdx.x * blockDim.x + threadIdx.x;
    int e = idx * 4;
    int b = e >> 21;
    float4 v = *(const float4*)(g_baseout + b*DMODEL + (e & 1023));
    *(float4*)(out + e) = v;
}

// -----------------------------------------------------------------------------
extern "C" void kernel_launch(void* const* d_in, const int* in_sizes, int n_in,
                              void* d_out, int out_size)
{
    const float* x    = (const float*)d_in[0];
    const float* Wq   = (const float*)d_in[1];
    const float* bq   = (const float*)d_in[2];
    const float* Wkv  = (const float*)d_in[3];
    const float* bkv  = (const float*)d_in[4];
    const float* Wout = (const float*)d_in[5];
    const float* bout = (const float*)d_in[6];
    const int*   idxs = (const int*)d_in[7];
    float* out = (float*)d_out;

    cudaFuncSetAttribute(gemm_tc<0>, cudaFuncAttributeMaxDynamicSharedMemorySize, NSTAGE*4*TILEB);
    cudaFuncSetAttribute(gemm_tc<1>, cudaFuncAttributeMaxDynamicSharedMemorySize, NSTAGE*3*TILEB);
    cudaFuncSetAttribute(gemm_tc<2>, cudaFuncAttributeMaxDynamicSharedMemorySize, NSTAGE*3*TILEB);
    int attn_smem = (UTOP*DHEAD + UTOP*KS_KEYS + 2*UTOP) * sizeof(float);
    cudaFuncSetAttribute(attn_flash, cudaFuncAttributeMaxDynamicSharedMemorySize, attn_smem);

    // conversions
    splitX<<<MROWS*DMODEL/256, 256>>>(x);
    splitWb<<<2*DD/256, 256>>>(Wq, Wkv);
    convH<<<2*DD/256, 256>>>(Wkv, Wout);

    // QK projection (bf16 3-pass) and V projection (fp16 2-pass)
    gemm_tc<0><<<dim3(2*DMODEL/128, MROWS/128), 256, NSTAGE*4*TILEB>>>(bq, bkv, nullptr);
    gemm_tc<1><<<dim3(DMODEL/128, MROWS/128), 256, NSTAGE*3*TILEB>>>(nullptr, bkv, nullptr);
    // sparsity measure + selection (fp32)
    score_m_kernel<<<BHL/8, 256>>>(idxs);
    topk_kernel<<<BATCH*NHEAD, 256>>>();
    // selection maps + compaction
    sel_clear<<<256, 256>>>();
    sel_mark<<<BATCH*NHEAD, UTOP>>>();
    compact_kernel<<<BATCH, 256>>>();
    // flash-split attention (also emits V-mean partials)
    attn_flash<<<dim3(KSPLIT, BATCH*NHEAD), 256, attn_smem>>>();
    vmean_fin<<<BATCH*NHEAD, 64>>>();
    attn_combine<<<BATCH*NHEAD*UTOP, 64>>>();
    // base output rows (exact fp32) + broadcast
    base_out_kernel<<<BATCH*DMODEL/8, 256>>>(Wout, bout);
    broadcast_base<<<MROWS*DMODEL/1024, 256>>>(out);
    // modified context rows -> fp16 split -> scatter GEMM
    build_cmod<<<BATCH*MODROWS*DMODEL/256, 256>>>();
    gemm_tc<2><<<dim3(DMODEL/128, BATCH*MODROWS/128), 256, NSTAGE*3*TILEB>>>(bout, nullptr, out);
}